// round 1
// baseline (speedup 1.0000x reference)
#include <cuda_runtime.h>
#include <math.h>

// ---------------- problem constants ----------------
#define T_TOK   2048            // B*S tokens
#define DM      1024            // d_model
#define HM      512             // d_hidden
#define ER      64              // routed experts
#define TOPK    6
#define ES      2               // shared experts
#define NGRP    (ER + ES)       // 66 expert groups (64 routed + 2 shared)
#define NPAIR_R (T_TOK * TOPK)  // 12288 routed pairs
#define NPAIR   (NPAIR_R + T_TOK * ES) // 16384 total pairs
#define EPSR    1.1920929e-07f

// ---------------- device scratch (no allocation allowed) ----------------
__device__ float g_xn[T_TOK * DM];       // rmsnorm'd tokens (8 MB)
__device__ int   g_idx[T_TOK * TOPK];    // top-k expert ids
__device__ float g_wk [T_TOK * TOPK];    // routing weights
__device__ int   g_cnt[NGRP];            // tokens per group
__device__ int   g_off[NGRP + 1];        // exclusive scan
__device__ int   g_fill[ER];             // scatter cursors
__device__ int   g_ptok[NPAIR];          // token id per pair (grouped by expert)
__device__ float g_pw  [NPAIR];          // weight per pair
__device__ float g_h   [(size_t)NPAIR * HM]; // raw hidden (32 MB)
__device__ float g_g   [(size_t)NPAIR * HM]; // gated hidden (32 MB)

// ---------------- kernel 0: reset counters ----------------
__global__ void k_zero() {
    int i = threadIdx.x;
    if (i < NGRP) g_cnt[i] = (i < ER) ? 0 : T_TOK; // shared experts take all tokens
}

// ---------------- kernel 1: RMSNorm + residual init ----------------
__global__ void __launch_bounds__(256) k_rmsnorm(const float* __restrict__ x,
                                                 const float* __restrict__ nw,
                                                 float* __restrict__ out) {
    int t = blockIdx.x, tid = threadIdx.x;
    const float4* xr = (const float4*)(x + (size_t)t * DM);
    float4 a = xr[tid]; // 256 threads * 4 = 1024
    float s = a.x * a.x + a.y * a.y + a.z * a.z + a.w * a.w;
    #pragma unroll
    for (int o = 16; o; o >>= 1) s += __shfl_xor_sync(0xffffffffu, s, o);
    __shared__ float ws[8];
    __shared__ float s_scale;
    if ((tid & 31) == 0) ws[tid >> 5] = s;
    __syncthreads();
    if (tid == 0) {
        float tot = 0.f;
        #pragma unroll
        for (int i = 0; i < 8; i++) tot += ws[i];
        s_scale = rsqrtf(tot / (float)DM + EPSR);
    }
    __syncthreads();
    float sc = s_scale;
    float4 w4 = ((const float4*)nw)[tid];
    float4 r;
    r.x = a.x * sc * w4.x; r.y = a.y * sc * w4.y;
    r.z = a.z * sc * w4.z; r.w = a.w * sc * w4.w;
    ((float4*)g_xn)[(size_t)t * 256 + tid] = r;
    ((float4*)out)[(size_t)t * 256 + tid]  = a;   // residual
}

// ---------------- kernel 2: router + top-k ----------------
__global__ void __launch_bounds__(256) k_router(const float* __restrict__ Wr,
                                                const float* __restrict__ bias) {
    __shared__ float sx[DM];
    __shared__ float part[ER][4];
    __shared__ float raw[ER];
    int t = blockIdx.x, tid = threadIdx.x;
    for (int i = tid; i < DM; i += 256) sx[i] = g_xn[(size_t)t * DM + i];
    __syncthreads();
    int e = tid & 63, pp = tid >> 6;
    const float* wr = Wr + (size_t)e * DM + pp * 256;
    const float* xs = sx + pp * 256;
    float s = 0.f;
    #pragma unroll 8
    for (int i = 0; i < 256; i++) s += xs[i] * wr[i];
    part[e][pp] = s;
    __syncthreads();
    if (tid < ER) raw[tid] = part[tid][0] + part[tid][1] + part[tid][2] + part[tid][3];
    __syncthreads();
    if (tid == 0) {
        bool sel[ER];
        #pragma unroll
        for (int i = 0; i < ER; i++) sel[i] = false;
        int   idx[TOPK];
        float sum = 0.f;
        for (int k = 0; k < TOPK; k++) {
            int best = 0; float bv = -1e30f;
            for (int e2 = 0; e2 < ER; e2++) {
                if (sel[e2]) continue;
                float a2 = raw[e2] + bias[e2];
                if (a2 > bv) { bv = a2; best = e2; }
            }
            sel[best] = true; idx[k] = best; sum += raw[best];
        }
        float inv = 1.f / sum;
        for (int k = 0; k < TOPK; k++) {
            g_idx[t * TOPK + k] = idx[k];
            g_wk [t * TOPK + k] = raw[idx[k]] * inv;
            atomicAdd(&g_cnt[idx[k]], 1);
        }
    }
}

// ---------------- kernel 3: scan ----------------
__global__ void k_scan() {
    if (threadIdx.x == 0) {
        int acc = 0;
        for (int i = 0; i < NGRP; i++) {
            g_off[i] = acc;
            if (i < ER) g_fill[i] = acc;
            acc += g_cnt[i];
        }
        g_off[NGRP] = acc; // == NPAIR
    }
}

// ---------------- kernel 4: scatter pairs grouped by expert ----------------
__global__ void k_scatter() {
    int p = blockIdx.x * 256 + threadIdx.x;
    if (p >= NPAIR) return;
    if (p < NPAIR_R) {
        int e = g_idx[p];
        int pos = atomicAdd(&g_fill[e], 1);
        g_ptok[pos] = p / TOPK;
        g_pw  [pos] = g_wk[p];
    } else {
        int q = p - NPAIR_R;           // shared pairs are already grouped
        g_ptok[p] = q % T_TOK;
        g_pw  [p] = 1.0f;
    }
}

// ---------------- tiled GEMM config ----------------
#define BM 64
#define BN 64
#define BKK 16
#define PADW 68

// ---------------- kernel 5: grouped GEMM1  h = xn @ W1[e] + b1 ----------------
__global__ void __launch_bounds__(256) k_gemm1(const float* __restrict__ rW1,
                                               const float* __restrict__ sW1,
                                               const float* __restrict__ rb1,
                                               const float* __restrict__ sb1) {
    __shared__ float As[BKK][PADW];
    __shared__ float Bs[BKK][PADW];
    __shared__ const float* Arow[BM];
    __shared__ int Prow[BM];
    int grp = blockIdx.z;
    int start = g_off[grp];
    int cnt = g_off[grp + 1] - start;
    const float* B  = (grp < ER) ? rW1 + (size_t)grp * DM * HM
                                 : sW1 + (size_t)(grp - ER) * DM * HM;
    const float* b1 = (grp < ER) ? rb1 + (size_t)grp * HM
                                 : sb1 + (size_t)(grp - ER) * HM;
    int nb = blockIdx.y * BN;
    int tid = threadIdx.x, tx = tid & 15, ty = tid >> 4;
    for (int mt = blockIdx.x; mt * BM < cnt; mt += gridDim.x) {
        int m0 = mt * BM;
        int rem = cnt - m0; if (rem > BM) rem = BM;
        __syncthreads();
        if (tid < BM) {
            if (tid < rem) {
                int p = start + m0 + tid;
                Prow[tid] = p;
                Arow[tid] = g_xn + (size_t)g_ptok[p] * DM;
            } else Arow[tid] = g_xn; // dummy (masked on load)
        }
        __syncthreads();
        float acc[4][4];
        #pragma unroll
        for (int i = 0; i < 4; i++)
            #pragma unroll
            for (int j = 0; j < 4; j++) acc[i][j] = 0.f;
        for (int kk = 0; kk < DM; kk += BKK) {
            #pragma unroll
            for (int l = 0; l < 4; l++) {
                int idx = tid + l * 256;
                int m = idx >> 4, k = idx & 15;
                As[k][m] = (m < rem) ? Arow[m][kk + k] : 0.f;
            }
            #pragma unroll
            for (int l = 0; l < 4; l++) {
                int idx = tid + l * 256;
                int k = idx >> 6, n = idx & 63;
                Bs[k][n] = B[(size_t)(kk + k) * HM + nb + n];
            }
            __syncthreads();
            #pragma unroll
            for (int k = 0; k < BKK; k++) {
                float4 a4 = *(float4*)&As[k][ty * 4];
                float4 b4 = *(float4*)&Bs[k][tx * 4];
                float av[4] = {a4.x, a4.y, a4.z, a4.w};
                float bv[4] = {b4.x, b4.y, b4.z, b4.w};
                #pragma unroll
                for (int i = 0; i < 4; i++)
                    #pragma unroll
                    for (int j = 0; j < 4; j++) acc[i][j] += av[i] * bv[j];
            }
            __syncthreads();
        }
        float4 bb = *(const float4*)&b1[nb + tx * 4];
        #pragma unroll
        for (int i = 0; i < 4; i++) {
            int m = ty * 4 + i;
            if (m < rem) {
                int p = Prow[m];
                float4 r;
                r.x = acc[i][0] + bb.x; r.y = acc[i][1] + bb.y;
                r.z = acc[i][2] + bb.z; r.w = acc[i][3] + bb.w;
                *(float4*)&g_h[(size_t)p * HM + nb + tx * 4] = r;
            }
        }
    }
}

// ---------------- kernel 6: gate GEMM  g = silu(h @ Wg) * h ----------------
__global__ void __launch_bounds__(256) k_gate(const float* __restrict__ rWg,
                                              const float* __restrict__ sWg) {
    __shared__ float As[BKK][PADW];
    __shared__ float Bs[BKK][PADW];
    int p0 = blockIdx.x * BM;                    // all rows valid (16384 total)
    const float* B = (p0 < NPAIR_R) ? rWg : sWg; // NPAIR_R is 64-aligned
    int nb = blockIdx.y * BN;
    int tid = threadIdx.x, tx = tid & 15, ty = tid >> 4;
    const float* Abase = g_h + (size_t)p0 * HM;
    float acc[4][4];
    #pragma unroll
    for (int i = 0; i < 4; i++)
        #pragma unroll
        for (int j = 0; j < 4; j++) acc[i][j] = 0.f;
    for (int kk = 0; kk < HM; kk += BKK) {
        #pragma unroll
        for (int l = 0; l < 4; l++) {
            int idx = tid + l * 256;
            int m = idx >> 4, k = idx & 15;
            As[k][m] = Abase[(size_t)m * HM + kk + k];
        }
        #pragma unroll
        for (int l = 0; l < 4; l++) {
            int idx = tid + l * 256;
            int k = idx >> 6, n = idx & 63;
            Bs[k][n] = B[(size_t)(kk + k) * HM + nb + n];
        }
        __syncthreads();
        #pragma unroll
        for (int k = 0; k < BKK; k++) {
            float4 a4 = *(float4*)&As[k][ty * 4];
            float4 b4 = *(float4*)&Bs[k][tx * 4];
            float av[4] = {a4.x, a4.y, a4.z, a4.w};
            float bv[4] = {b4.x, b4.y, b4.z, b4.w};
            #pragma unroll
            for (int i = 0; i < 4; i++)
                #pragma unroll
                for (int j = 0; j < 4; j++) acc[i][j] += av[i] * bv[j];
        }
        __syncthreads();
    }
    #pragma unroll
    for (int i = 0; i < 4; i++) {
        int m = ty * 4 + i;
        size_t base = (size_t)(p0 + m) * HM + nb + tx * 4;
        float4 h4 = *(float4*)&g_h[base];
        float4 r;
        r.x = (acc[i][0] / (1.f + expf(-acc[i][0]))) * h4.x;
        r.y = (acc[i][1] / (1.f + expf(-acc[i][1]))) * h4.y;
        r.z = (acc[i][2] / (1.f + expf(-acc[i][2]))) * h4.z;
        r.w = (acc[i][3] / (1.f + expf(-acc[i][3]))) * h4.w;
        *(float4*)&g_g[base] = r;
    }
}

// ---------------- kernel 7: grouped GEMM2  out += w * (g @ W2[e] + b2) ----------------
__global__ void __launch_bounds__(256) k_gemm2(const float* __restrict__ rW2,
                                               const float* __restrict__ sW2,
                                               const float* __restrict__ rb2,
                                               const float* __restrict__ sb2,
                                               float* __restrict__ out) {
    __shared__ float As[BKK][PADW];
    __shared__ float Bs[BKK][PADW];
    __shared__ int   Ptok[BM];
    __shared__ float Pw[BM];
    int grp = blockIdx.z;
    int start = g_off[grp];
    int cnt = g_off[grp + 1] - start;
    const float* B  = (grp < ER) ? rW2 + (size_t)grp * HM * DM
                                 : sW2 + (size_t)(grp - ER) * HM * DM;
    const float* b2 = (grp < ER) ? rb2 + (size_t)grp * DM
                                 : sb2 + (size_t)(grp - ER) * DM;
    int nb = blockIdx.y * BN;
    int tid = threadIdx.x, tx = tid & 15, ty = tid >> 4;
    for (int mt = blockIdx.x; mt * BM < cnt; mt += gridDim.x) {
        int m0 = mt * BM;
        int rem = cnt - m0; if (rem > BM) rem = BM;
        __syncthreads();
        if (tid < BM && tid < rem) {
            int p = start + m0 + tid;
            Ptok[tid] = g_ptok[p];
            Pw[tid]   = g_pw[p];
        }
        __syncthreads();
        float acc[4][4];
        #pragma unroll
        for (int i = 0; i < 4; i++)
            #pragma unroll
            for (int j = 0; j < 4; j++) acc[i][j] = 0.f;
        const float* Abase = g_g + (size_t)(start + m0) * HM;
        for (int kk = 0; kk < HM; kk += BKK) {
            #pragma unroll
            for (int l = 0; l < 4; l++) {
                int idx = tid + l * 256;
                int m = idx >> 4, k = idx & 15;
                As[k][m] = (m < rem) ? Abase[(size_t)m * HM + kk + k] : 0.f;
            }
            #pragma unroll
            for (int l = 0; l < 4; l++) {
                int idx = tid + l * 256;
                int k = idx >> 6, n = idx & 63;
                Bs[k][n] = B[(size_t)(kk + k) * DM + nb + n];
            }
            __syncthreads();
            #pragma unroll
            for (int k = 0; k < BKK; k++) {
                float4 a4 = *(float4*)&As[k][ty * 4];
                float4 b4 = *(float4*)&Bs[k][tx * 4];
                float av[4] = {a4.x, a4.y, a4.z, a4.w};
                float bv[4] = {b4.x, b4.y, b4.z, b4.w};
                #pragma unroll
                for (int i = 0; i < 4; i++)
                    #pragma unroll
                    for (int j = 0; j < 4; j++) acc[i][j] += av[i] * bv[j];
            }
            __syncthreads();
        }
        float4 bb = *(const float4*)&b2[nb + tx * 4];
        float bbv[4] = {bb.x, bb.y, bb.z, bb.w};
        #pragma unroll
        for (int i = 0; i < 4; i++) {
            int m = ty * 4 + i;
            if (m < rem) {
                float w = Pw[m];
                float* orow = out + (size_t)Ptok[m] * DM + nb + tx * 4;
                #pragma unroll
                for (int j = 0; j < 4; j++)
                    atomicAdd(&orow[j], (acc[i][j] + bbv[j]) * w);
            }
        }
    }
}

// ---------------- launcher ----------------
extern "C" void kernel_launch(void* const* d_in, const int* in_sizes, int n_in,
                              void* d_out, int out_size) {
    const float* x      = (const float*)d_in[0];
    const float* norm_w = (const float*)d_in[1];
    const float* Wr     = (const float*)d_in[2];
    const float* sW1    = (const float*)d_in[3];
    const float* sb1    = (const float*)d_in[4];
    const float* sW2    = (const float*)d_in[5];
    const float* sb2    = (const float*)d_in[6];
    const float* sWg    = (const float*)d_in[7];
    const float* rW1    = (const float*)d_in[8];
    const float* rb1    = (const float*)d_in[9];
    const float* rW2    = (const float*)d_in[10];
    const float* rb2    = (const float*)d_in[11];
    const float* rWg    = (const float*)d_in[12];
    const float* bias   = (const float*)d_in[13];
    float* out = (float*)d_out;

    k_zero<<<1, 128>>>();
    k_rmsnorm<<<T_TOK, 256>>>(x, norm_w, out);
    k_router<<<T_TOK, 256>>>(Wr, bias);
    k_scan<<<1, 32>>>();
    k_scatter<<<(NPAIR + 255) / 256, 256>>>();
    k_gemm1<<<dim3(32, HM / BN, NGRP), 256>>>(rW1, sW1, rb1, sb1);
    k_gate<<<dim3(NPAIR / BM, HM / BN), 256>>>(rWg, sWg);
    k_gemm2<<<dim3(32, DM / BN, NGRP), 256>>>(rW2, sW2, rb2, sb2, out);
}

// round 2
// speedup vs baseline: 3.1943x; 3.1943x over previous
#include <cuda_runtime.h>
#include <math.h>
#include <stdint.h>

// ---------------- problem constants ----------------
#define T_TOK   2048
#define DM      1024
#define HM      512
#define ER      64
#define TOPK    6
#define ES      2
#define NGRP    (ER + ES)
#define NPAIR_R (T_TOK * TOPK)
#define NPAIR   (NPAIR_R + T_TOK * ES)
#define EPSR    1.1920929e-07f

// ---------------- device scratch ----------------
__device__ float g_xn[T_TOK * DM];
__device__ float g_raw[T_TOK * ER];
__device__ int   g_idx[T_TOK * TOPK];
__device__ float g_wk [T_TOK * TOPK];
__device__ int   g_cnt[NGRP];
__device__ int   g_off[NGRP + 1];
__device__ int   g_fill[ER];
__device__ int   g_ptok[NPAIR];
__device__ float g_pw  [NPAIR];
__device__ int   g_pos [T_TOK * 8];               // 6 routed + 2 shared pair rows per token
__device__ float g_h   [(size_t)NPAIR * HM];
__device__ float g_g   [(size_t)NPAIR * HM];
__device__ float g_po  [(size_t)NPAIR * DM];      // per-pair outputs

// ---------------- helpers ----------------
__device__ __forceinline__ uint4 cvt4(float4 v) {
    uint4 o;
    asm("cvt.rna.tf32.f32 %0, %1;" : "=r"(o.x) : "f"(v.x));
    asm("cvt.rna.tf32.f32 %0, %1;" : "=r"(o.y) : "f"(v.y));
    asm("cvt.rna.tf32.f32 %0, %1;" : "=r"(o.z) : "f"(v.z));
    asm("cvt.rna.tf32.f32 %0, %1;" : "=r"(o.w) : "f"(v.w));
    return o;
}

__device__ __forceinline__ void mma_tf32(float* c, uint32_t a0, uint32_t a1,
                                         uint32_t a2, uint32_t a3,
                                         uint32_t b0, uint32_t b1) {
    asm volatile(
        "mma.sync.aligned.m16n8k8.row.col.f32.tf32.tf32.f32 "
        "{%0,%1,%2,%3}, {%4,%5,%6,%7}, {%8,%9}, {%0,%1,%2,%3};\n"
        : "+f"(c[0]), "+f"(c[1]), "+f"(c[2]), "+f"(c[3])
        : "r"(a0), "r"(a1), "r"(a2), "r"(a3), "r"(b0), "r"(b1));
}

// ---------------- kernel 0: reset counters ----------------
__global__ void k_zero() {
    int i = threadIdx.x;
    if (i < NGRP) g_cnt[i] = (i < ER) ? 0 : T_TOK;
}

// ---------------- kernel 1: RMSNorm + residual init ----------------
__global__ void __launch_bounds__(256) k_rmsnorm(const float* __restrict__ x,
                                                 const float* __restrict__ nw,
                                                 float* __restrict__ out) {
    int t = blockIdx.x, tid = threadIdx.x;
    const float4* xr = (const float4*)(x + (size_t)t * DM);
    float4 a = xr[tid];
    float s = a.x * a.x + a.y * a.y + a.z * a.z + a.w * a.w;
    #pragma unroll
    for (int o = 16; o; o >>= 1) s += __shfl_xor_sync(0xffffffffu, s, o);
    __shared__ float ws[8];
    __shared__ float s_scale;
    if ((tid & 31) == 0) ws[tid >> 5] = s;
    __syncthreads();
    if (tid == 0) {
        float tot = 0.f;
        #pragma unroll
        for (int i = 0; i < 8; i++) tot += ws[i];
        s_scale = rsqrtf(tot / (float)DM + EPSR);
    }
    __syncthreads();
    float sc = s_scale;
    float4 w4 = ((const float4*)nw)[tid];
    float4 r;
    r.x = a.x * sc * w4.x; r.y = a.y * sc * w4.y;
    r.z = a.z * sc * w4.z; r.w = a.w * sc * w4.w;
    ((float4*)g_xn)[(size_t)t * 256 + tid] = r;
    ((float4*)out)[(size_t)t * 256 + tid]  = a;
}

// ---------------- kernel 2: router raw affinities (fp32 GEMM, 2048x64x1024) ----
#define RPAD 68
__global__ void __launch_bounds__(256) k_raw(const float* __restrict__ Wr) {
    __shared__ float As[16][RPAD];   // [k][m]
    __shared__ float Bs[16][RPAD];   // [k][e]
    int t0 = blockIdx.x * 64;
    int tid = threadIdx.x, tx = tid & 15, ty = tid >> 4;
    float acc[4][4];
    #pragma unroll
    for (int i = 0; i < 4; i++)
        #pragma unroll
        for (int j = 0; j < 4; j++) acc[i][j] = 0.f;
    int m = tid >> 2, kv = tid & 3;
    for (int kk = 0; kk < DM; kk += 16) {
        float4 av = *(const float4*)(g_xn + (size_t)(t0 + m) * DM + kk + kv * 4);
        float4 bv = *(const float4*)(Wr + (size_t)m * DM + kk + kv * 4);
        As[kv * 4 + 0][m] = av.x; As[kv * 4 + 1][m] = av.y;
        As[kv * 4 + 2][m] = av.z; As[kv * 4 + 3][m] = av.w;
        Bs[kv * 4 + 0][m] = bv.x; Bs[kv * 4 + 1][m] = bv.y;
        Bs[kv * 4 + 2][m] = bv.z; Bs[kv * 4 + 3][m] = bv.w;
        __syncthreads();
        #pragma unroll
        for (int k = 0; k < 16; k++) {
            float4 a4 = *(float4*)&As[k][ty * 4];
            float4 b4 = *(float4*)&Bs[k][tx * 4];
            float aa[4] = {a4.x, a4.y, a4.z, a4.w};
            float bb[4] = {b4.x, b4.y, b4.z, b4.w};
            #pragma unroll
            for (int i = 0; i < 4; i++)
                #pragma unroll
                for (int j = 0; j < 4; j++) acc[i][j] += aa[i] * bb[j];
        }
        __syncthreads();
    }
    #pragma unroll
    for (int i = 0; i < 4; i++)
        #pragma unroll
        for (int j = 0; j < 4; j++)
            g_raw[(size_t)(t0 + ty * 4 + i) * ER + tx * 4 + j] = acc[i][j];
}

// ---------------- kernel 3: top-6 per token (one warp per token) ----------------
__global__ void __launch_bounds__(256) k_topk(const float* __restrict__ bias) {
    int tid = threadIdx.x, lane = tid & 31, wid = tid >> 5;
    int t = blockIdx.x * 8 + wid;
    float r0 = g_raw[(size_t)t * ER + lane];
    float r1 = g_raw[(size_t)t * ER + lane + 32];
    float a0 = r0 + bias[lane];
    float a1 = r1 + bias[lane + 32];
    float sum = 0.f;
    int   sel_e[TOPK];
    float sel_r[TOPK];
    #pragma unroll
    for (int k = 0; k < TOPK; k++) {
        float v; int e;
        if (a0 >= a1) { v = a0; e = lane; } else { v = a1; e = lane + 32; }
        #pragma unroll
        for (int o = 16; o; o >>= 1) {
            float ov = __shfl_xor_sync(0xffffffffu, v, o);
            int   oe = __shfl_xor_sync(0xffffffffu, e, o);
            if (ov > v || (ov == v && oe < e)) { v = ov; e = oe; }
        }
        if (e == lane)      a0 = -1e30f;
        if (e == lane + 32) a1 = -1e30f;
        float ra = __shfl_sync(0xffffffffu, r0, e & 31);
        float rb = __shfl_sync(0xffffffffu, r1, e & 31);
        float rs = (e < 32) ? ra : rb;
        sel_e[k] = e; sel_r[k] = rs; sum += rs;
    }
    float inv = 1.f / sum;
    if (lane < TOPK) {
        g_idx[t * TOPK + lane] = sel_e[lane];
        g_wk [t * TOPK + lane] = sel_r[lane] * inv;
        atomicAdd(&g_cnt[sel_e[lane]], 1);
    }
}

// ---------------- kernel 4: scan ----------------
__global__ void k_scan() {
    if (threadIdx.x == 0) {
        int acc = 0;
        for (int i = 0; i < NGRP; i++) {
            g_off[i] = acc;
            if (i < ER) g_fill[i] = acc;
            acc += g_cnt[i];
        }
        g_off[NGRP] = acc;
    }
}

// ---------------- kernel 5: scatter ----------------
__global__ void k_scatter() {
    int p = blockIdx.x * 256 + threadIdx.x;
    if (p >= NPAIR) return;
    if (p < NPAIR_R) {
        int t = p / TOPK, k = p % TOPK;
        int e = g_idx[p];
        int pos = atomicAdd(&g_fill[e], 1);
        g_ptok[pos] = t;
        g_pw  [pos] = g_wk[p];
        g_pos[t * 8 + k] = pos;
    } else {
        int q = p - NPAIR_R;
        int j = q / T_TOK, t = q % T_TOK;
        g_ptok[p] = t;
        g_pw  [p] = 1.0f;
        g_pos[t * 8 + TOPK + j] = p;
    }
}

// ================= tf32 tensor-core GEMM tiles =================
// block tile 64x64, BK=32, 256 threads = 8 warps (4 warp_m x 2 warp_n)
#define ASTR 36
#define BSTR 72

// ---------------- kernel 6: grouped GEMM1  h = gather(xn) @ W1[e] + b1 ----------
__global__ void __launch_bounds__(256) k_gemm1(const float* __restrict__ rW1,
                                               const float* __restrict__ sW1,
                                               const float* __restrict__ rb1,
                                               const float* __restrict__ sb1) {
    __shared__ uint32_t As[64 * ASTR];
    __shared__ uint32_t Bs[32 * BSTR];
    __shared__ const float* Arow[64];
    int grp = blockIdx.z;
    int start = g_off[grp];
    int cnt = g_off[grp + 1] - start;
    const float* B  = (grp < ER) ? rW1 + (size_t)grp * DM * HM
                                 : sW1 + (size_t)(grp - ER) * DM * HM;
    const float* b1 = (grp < ER) ? rb1 + (size_t)grp * HM
                                 : sb1 + (size_t)(grp - ER) * HM;
    int nb = blockIdx.y * 64;
    int tid = threadIdx.x, lane = tid & 31, wid = tid >> 5;
    int warp_m = wid >> 1, warp_n = wid & 1;
    int gid = lane >> 2, tig = lane & 3;
    int row0 = warp_m * 16 + gid;

    for (int mt = blockIdx.x; mt * 64 < cnt; mt += gridDim.x) {
        int m0 = mt * 64;
        int rem = cnt - m0; if (rem > 64) rem = 64;
        __syncthreads();
        if (tid < 64)
            Arow[tid] = (tid < rem) ? g_xn + (size_t)g_ptok[start + m0 + tid] * DM
                                    : g_xn;
        __syncthreads();
        float acc[4][4];
        #pragma unroll
        for (int i = 0; i < 4; i++)
            #pragma unroll
            for (int j = 0; j < 4; j++) acc[i][j] = 0.f;
        for (int kk = 0; kk < DM; kk += 32) {
            #pragma unroll
            for (int l = 0; l < 2; l++) {
                int idx = tid + l * 256;
                int m = idx >> 3, kv = idx & 7;
                float4 v = (m < rem) ? *(const float4*)(Arow[m] + kk + kv * 4)
                                     : make_float4(0.f, 0.f, 0.f, 0.f);
                *(uint4*)&As[m * ASTR + kv * 4] = cvt4(v);
            }
            #pragma unroll
            for (int l = 0; l < 2; l++) {
                int idx = tid + l * 256;
                int k = idx >> 4, nv = idx & 15;
                float4 v = *(const float4*)(B + (size_t)(kk + k) * HM + nb + nv * 4);
                *(uint4*)&Bs[k * BSTR + nv * 4] = cvt4(v);
            }
            __syncthreads();
            #pragma unroll
            for (int ks = 0; ks < 4; ks++) {
                int kb = ks * 8;
                uint32_t a0 = As[row0 * ASTR + kb + tig];
                uint32_t a1 = As[(row0 + 8) * ASTR + kb + tig];
                uint32_t a2 = As[row0 * ASTR + kb + tig + 4];
                uint32_t a3 = As[(row0 + 8) * ASTR + kb + tig + 4];
                #pragma unroll
                for (int nt = 0; nt < 4; nt++) {
                    int nc = warp_n * 32 + nt * 8 + gid;
                    uint32_t b0 = Bs[(kb + tig) * BSTR + nc];
                    uint32_t b1r = Bs[(kb + tig + 4) * BSTR + nc];
                    mma_tf32(acc[nt], a0, a1, a2, a3, b0, b1r);
                }
            }
            __syncthreads();
        }
        #pragma unroll
        for (int nt = 0; nt < 4; nt++) {
            int col = nb + warp_n * 32 + nt * 8 + 2 * tig;
            float2 bv = *(const float2*)&b1[col];
            if (row0 < rem) {
                int p = start + m0 + row0;
                float2 r = make_float2(acc[nt][0] + bv.x, acc[nt][1] + bv.y);
                *(float2*)&g_h[(size_t)p * HM + col] = r;
            }
            if (row0 + 8 < rem) {
                int p = start + m0 + row0 + 8;
                float2 r = make_float2(acc[nt][2] + bv.x, acc[nt][3] + bv.y);
                *(float2*)&g_h[(size_t)p * HM + col] = r;
            }
        }
    }
}

// ---------------- kernel 7: gate  g = silu(h @ Wg) * h ----------------
__global__ void __launch_bounds__(256) k_gate(const float* __restrict__ rWg,
                                              const float* __restrict__ sWg) {
    __shared__ uint32_t As[64 * ASTR];
    __shared__ uint32_t Bs[32 * BSTR];
    int p0 = blockIdx.x * 64;
    const float* B = (p0 < NPAIR_R) ? rWg : sWg;
    int nb = blockIdx.y * 64;
    int tid = threadIdx.x, lane = tid & 31, wid = tid >> 5;
    int warp_m = wid >> 1, warp_n = wid & 1;
    int gid = lane >> 2, tig = lane & 3;
    int row0 = warp_m * 16 + gid;
    const float* Abase = g_h + (size_t)p0 * HM;

    float acc[4][4];
    #pragma unroll
    for (int i = 0; i < 4; i++)
        #pragma unroll
        for (int j = 0; j < 4; j++) acc[i][j] = 0.f;
    for (int kk = 0; kk < HM; kk += 32) {
        #pragma unroll
        for (int l = 0; l < 2; l++) {
            int idx = tid + l * 256;
            int m = idx >> 3, kv = idx & 7;
            float4 v = *(const float4*)(Abase + (size_t)m * HM + kk + kv * 4);
            *(uint4*)&As[m * ASTR + kv * 4] = cvt4(v);
        }
        #pragma unroll
        for (int l = 0; l < 2; l++) {
            int idx = tid + l * 256;
            int k = idx >> 4, nv = idx & 15;
            float4 v = *(const float4*)(B + (size_t)(kk + k) * HM + nb + nv * 4);
            *(uint4*)&Bs[k * BSTR + nv * 4] = cvt4(v);
        }
        __syncthreads();
        #pragma unroll
        for (int ks = 0; ks < 4; ks++) {
            int kb = ks * 8;
            uint32_t a0 = As[row0 * ASTR + kb + tig];
            uint32_t a1 = As[(row0 + 8) * ASTR + kb + tig];
            uint32_t a2 = As[row0 * ASTR + kb + tig + 4];
            uint32_t a3 = As[(row0 + 8) * ASTR + kb + tig + 4];
            #pragma unroll
            for (int nt = 0; nt < 4; nt++) {
                int nc = warp_n * 32 + nt * 8 + gid;
                uint32_t b0 = Bs[(kb + tig) * BSTR + nc];
                uint32_t b1r = Bs[(kb + tig + 4) * BSTR + nc];
                mma_tf32(acc[nt], a0, a1, a2, a3, b0, b1r);
            }
        }
        __syncthreads();
    }
    #pragma unroll
    for (int nt = 0; nt < 4; nt++) {
        int col = nb + warp_n * 32 + nt * 8 + 2 * tig;
        {
            size_t base = (size_t)(p0 + row0) * HM + col;
            float2 h2 = *(float2*)&g_h[base];
            float2 r;
            r.x = (acc[nt][0] / (1.f + __expf(-acc[nt][0]))) * h2.x;
            r.y = (acc[nt][1] / (1.f + __expf(-acc[nt][1]))) * h2.y;
            *(float2*)&g_g[base] = r;
        }
        {
            size_t base = (size_t)(p0 + row0 + 8) * HM + col;
            float2 h2 = *(float2*)&g_h[base];
            float2 r;
            r.x = (acc[nt][2] / (1.f + __expf(-acc[nt][2]))) * h2.x;
            r.y = (acc[nt][3] / (1.f + __expf(-acc[nt][3]))) * h2.y;
            *(float2*)&g_g[base] = r;
        }
    }
}

// ---------------- kernel 8: grouped GEMM2  po = (g @ W2[e] + b2) * w ----------
__global__ void __launch_bounds__(256) k_gemm2(const float* __restrict__ rW2,
                                               const float* __restrict__ sW2,
                                               const float* __restrict__ rb2,
                                               const float* __restrict__ sb2) {
    __shared__ uint32_t As[64 * ASTR];
    __shared__ uint32_t Bs[32 * BSTR];
    __shared__ float Pw[64];
    int grp = blockIdx.z;
    int start = g_off[grp];
    int cnt = g_off[grp + 1] - start;
    const float* B  = (grp < ER) ? rW2 + (size_t)grp * HM * DM
                                 : sW2 + (size_t)(grp - ER) * HM * DM;
    const float* b2 = (grp < ER) ? rb2 + (size_t)grp * DM
                                 : sb2 + (size_t)(grp - ER) * DM;
    int nb = blockIdx.y * 64;
    int tid = threadIdx.x, lane = tid & 31, wid = tid >> 5;
    int warp_m = wid >> 1, warp_n = wid & 1;
    int gid = lane >> 2, tig = lane & 3;
    int row0 = warp_m * 16 + gid;

    for (int mt = blockIdx.x; mt * 64 < cnt; mt += gridDim.x) {
        int m0 = mt * 64;
        int rem = cnt - m0; if (rem > 64) rem = 64;
        __syncthreads();
        if (tid < 64 && tid < rem) Pw[tid] = g_pw[start + m0 + tid];
        __syncthreads();
        float acc[4][4];
        #pragma unroll
        for (int i = 0; i < 4; i++)
            #pragma unroll
            for (int j = 0; j < 4; j++) acc[i][j] = 0.f;
        const float* Abase = g_g + (size_t)(start + m0) * HM;
        for (int kk = 0; kk < HM; kk += 32) {
            #pragma unroll
            for (int l = 0; l < 2; l++) {
                int idx = tid + l * 256;
                int m = idx >> 3, kv = idx & 7;
                float4 v = (m < rem) ? *(const float4*)(Abase + (size_t)m * HM + kk + kv * 4)
                                     : make_float4(0.f, 0.f, 0.f, 0.f);
                *(uint4*)&As[m * ASTR + kv * 4] = cvt4(v);
            }
            #pragma unroll
            for (int l = 0; l < 2; l++) {
                int idx = tid + l * 256;
                int k = idx >> 4, nv = idx & 15;
                float4 v = *(const float4*)(B + (size_t)(kk + k) * DM + nb + nv * 4);
                *(uint4*)&Bs[k * BSTR + nv * 4] = cvt4(v);
            }
            __syncthreads();
            #pragma unroll
            for (int ks = 0; ks < 4; ks++) {
                int kb = ks * 8;
                uint32_t a0 = As[row0 * ASTR + kb + tig];
                uint32_t a1 = As[(row0 + 8) * ASTR + kb + tig];
                uint32_t a2 = As[row0 * ASTR + kb + tig + 4];
                uint32_t a3 = As[(row0 + 8) * ASTR + kb + tig + 4];
                #pragma unroll
                for (int nt = 0; nt < 4; nt++) {
                    int nc = warp_n * 32 + nt * 8 + gid;
                    uint32_t b0 = Bs[(kb + tig) * BSTR + nc];
                    uint32_t b1r = Bs[(kb + tig + 4) * BSTR + nc];
                    mma_tf32(acc[nt], a0, a1, a2, a3, b0, b1r);
                }
            }
            __syncthreads();
        }
        #pragma unroll
        for (int nt = 0; nt < 4; nt++) {
            int col = nb + warp_n * 32 + nt * 8 + 2 * tig;
            float2 bv = *(const float2*)&b2[col];
            if (row0 < rem) {
                int p = start + m0 + row0;
                float w = Pw[row0];
                float2 r = make_float2((acc[nt][0] + bv.x) * w, (acc[nt][1] + bv.y) * w);
                *(float2*)&g_po[(size_t)p * DM + col] = r;
            }
            if (row0 + 8 < rem) {
                int p = start + m0 + row0 + 8;
                float w = Pw[row0 + 8];
                float2 r = make_float2((acc[nt][2] + bv.x) * w, (acc[nt][3] + bv.y) * w);
                *(float2*)&g_po[(size_t)p * DM + col] = r;
            }
        }
    }
}

// ---------------- kernel 9: per-token reduce of 8 pair rows ----------------
__global__ void __launch_bounds__(256) k_reduce(float* __restrict__ out) {
    int t = blockIdx.x, tid = threadIdx.x;
    __shared__ int pos[8];
    if (tid < 8) pos[tid] = g_pos[t * 8 + tid];
    __syncthreads();
    size_t d0 = (size_t)tid * 4;
    float4 s = *(float4*)&out[(size_t)t * DM + d0];   // residual x
    #pragma unroll
    for (int j = 0; j < 8; j++) {
        float4 v = *(const float4*)&g_po[(size_t)pos[j] * DM + d0];
        s.x += v.x; s.y += v.y; s.z += v.z; s.w += v.w;
    }
    *(float4*)&out[(size_t)t * DM + d0] = s;
}

// ---------------- launcher ----------------
extern "C" void kernel_launch(void* const* d_in, const int* in_sizes, int n_in,
                              void* d_out, int out_size) {
    const float* x      = (const float*)d_in[0];
    const float* norm_w = (const float*)d_in[1];
    const float* Wr     = (const float*)d_in[2];
    const float* sW1    = (const float*)d_in[3];
    const float* sb1    = (const float*)d_in[4];
    const float* sW2    = (const float*)d_in[5];
    const float* sb2    = (const float*)d_in[6];
    const float* sWg    = (const float*)d_in[7];
    const float* rW1    = (const float*)d_in[8];
    const float* rb1    = (const float*)d_in[9];
    const float* rW2    = (const float*)d_in[10];
    const float* rb2    = (const float*)d_in[11];
    const float* rWg    = (const float*)d_in[12];
    const float* bias   = (const float*)d_in[13];
    float* out = (float*)d_out;

    k_zero<<<1, 128>>>();
    k_rmsnorm<<<T_TOK, 256>>>(x, norm_w, out);
    k_raw<<<T_TOK / 64, 256>>>(Wr);
    k_topk<<<T_TOK / 8, 256>>>(bias);
    k_scan<<<1, 32>>>();
    k_scatter<<<(NPAIR + 255) / 256, 256>>>();
    k_gemm1<<<dim3(16, HM / 64, NGRP), 256>>>(rW1, sW1, rb1, sb1);
    k_gate<<<dim3(NPAIR / 64, HM / 64), 256>>>(rWg, sWg);
    k_gemm2<<<dim3(16, DM / 64, NGRP), 256>>>(rW2, sW2, rb2, sb2);
    k_reduce<<<T_TOK, 256>>>(out);
}

// round 3
// speedup vs baseline: 3.4126x; 1.0684x over previous
#include <cuda_runtime.h>
#include <math.h>
#include <stdint.h>

// ---------------- problem constants ----------------
#define T_TOK   2048
#define DM      1024
#define HM      512
#define ER      64
#define TOPK    6
#define ES      2
#define NGRP    (ER + ES)
#define NPAIR_R (T_TOK * TOPK)
#define NPAIR   (NPAIR_R + T_TOK * ES)
#define EPSR    1.1920929e-07f

// ---------------- device scratch ----------------
__device__ float g_xn[T_TOK * DM];
__device__ float g_raw[T_TOK * ER];
__device__ int   g_idx[T_TOK * TOPK];
__device__ float g_wk [T_TOK * TOPK];
__device__ int   g_cnt[NGRP];
__device__ int   g_off[NGRP + 1];
__device__ int   g_fill[ER];
__device__ int   g_ptok[NPAIR];
__device__ float g_pw  [NPAIR];
__device__ int   g_pos [T_TOK * 8];
__device__ float g_h   [(size_t)NPAIR * HM];
__device__ float g_g   [(size_t)NPAIR * HM];
__device__ float g_po  [(size_t)NPAIR * DM];

// ---------------- helpers ----------------
__device__ __forceinline__ uint32_t pk(float lo, float hi) {
    uint32_t r;
    asm("cvt.rn.bf16x2.f32 %0, %1, %2;" : "=r"(r) : "f"(hi), "f"(lo));
    return r;
}

__device__ __forceinline__ void mma_bf16(float* c, uint32_t a0, uint32_t a1,
                                         uint32_t a2, uint32_t a3,
                                         uint32_t b0, uint32_t b1) {
    asm volatile(
        "mma.sync.aligned.m16n8k16.row.col.f32.bf16.bf16.f32 "
        "{%0,%1,%2,%3}, {%4,%5,%6,%7}, {%8,%9}, {%0,%1,%2,%3};\n"
        : "+f"(c[0]), "+f"(c[1]), "+f"(c[2]), "+f"(c[3])
        : "r"(a0), "r"(a1), "r"(a2), "r"(a3), "r"(b0), "r"(b1));
}

// ---------------- kernel 0 ----------------
__global__ void k_zero() {
    int i = threadIdx.x;
    if (i < NGRP) g_cnt[i] = (i < ER) ? 0 : T_TOK;
}

// ---------------- kernel 1: RMSNorm + residual init ----------------
__global__ void __launch_bounds__(256) k_rmsnorm(const float* __restrict__ x,
                                                 const float* __restrict__ nw,
                                                 float* __restrict__ out) {
    int t = blockIdx.x, tid = threadIdx.x;
    const float4* xr = (const float4*)(x + (size_t)t * DM);
    float4 a = xr[tid];
    float s = a.x * a.x + a.y * a.y + a.z * a.z + a.w * a.w;
    #pragma unroll
    for (int o = 16; o; o >>= 1) s += __shfl_xor_sync(0xffffffffu, s, o);
    __shared__ float ws[8];
    __shared__ float s_scale;
    if ((tid & 31) == 0) ws[tid >> 5] = s;
    __syncthreads();
    if (tid == 0) {
        float tot = 0.f;
        #pragma unroll
        for (int i = 0; i < 8; i++) tot += ws[i];
        s_scale = rsqrtf(tot / (float)DM + EPSR);
    }
    __syncthreads();
    float sc = s_scale;
    float4 w4 = ((const float4*)nw)[tid];
    float4 r;
    r.x = a.x * sc * w4.x; r.y = a.y * sc * w4.y;
    r.z = a.z * sc * w4.z; r.w = a.w * sc * w4.w;
    ((float4*)g_xn)[(size_t)t * 256 + tid] = r;
    ((float4*)out)[(size_t)t * 256 + tid]  = a;
}

// ---------------- kernel 2: router raw affinities (fp32, bit-safe) ----------
#define RPAD 68
__global__ void __launch_bounds__(256) k_raw(const float* __restrict__ Wr) {
    __shared__ float As[16][RPAD];
    __shared__ float Bs[16][RPAD];
    int t0 = blockIdx.x * 64;
    int tid = threadIdx.x, tx = tid & 15, ty = tid >> 4;
    float acc[4][4];
    #pragma unroll
    for (int i = 0; i < 4; i++)
        #pragma unroll
        for (int j = 0; j < 4; j++) acc[i][j] = 0.f;
    int m = tid >> 2, kv = tid & 3;
    for (int kk = 0; kk < DM; kk += 16) {
        float4 av = *(const float4*)(g_xn + (size_t)(t0 + m) * DM + kk + kv * 4);
        float4 bv = *(const float4*)(Wr + (size_t)m * DM + kk + kv * 4);
        As[kv * 4 + 0][m] = av.x; As[kv * 4 + 1][m] = av.y;
        As[kv * 4 + 2][m] = av.z; As[kv * 4 + 3][m] = av.w;
        Bs[kv * 4 + 0][m] = bv.x; Bs[kv * 4 + 1][m] = bv.y;
        Bs[kv * 4 + 2][m] = bv.z; Bs[kv * 4 + 3][m] = bv.w;
        __syncthreads();
        #pragma unroll
        for (int k = 0; k < 16; k++) {
            float4 a4 = *(float4*)&As[k][ty * 4];
            float4 b4 = *(float4*)&Bs[k][tx * 4];
            float aa[4] = {a4.x, a4.y, a4.z, a4.w};
            float bb[4] = {b4.x, b4.y, b4.z, b4.w};
            #pragma unroll
            for (int i = 0; i < 4; i++)
                #pragma unroll
                for (int j = 0; j < 4; j++) acc[i][j] += aa[i] * bb[j];
        }
        __syncthreads();
    }
    #pragma unroll
    for (int i = 0; i < 4; i++)
        #pragma unroll
        for (int j = 0; j < 4; j++)
            g_raw[(size_t)(t0 + ty * 4 + i) * ER + tx * 4 + j] = acc[i][j];
}

// ---------------- kernel 3: top-6 per token ----------------
__global__ void __launch_bounds__(256) k_topk(const float* __restrict__ bias) {
    int tid = threadIdx.x, lane = tid & 31, wid = tid >> 5;
    int t = blockIdx.x * 8 + wid;
    float r0 = g_raw[(size_t)t * ER + lane];
    float r1 = g_raw[(size_t)t * ER + lane + 32];
    float a0 = r0 + bias[lane];
    float a1 = r1 + bias[lane + 32];
    float sum = 0.f;
    int   sel_e[TOPK];
    float sel_r[TOPK];
    #pragma unroll
    for (int k = 0; k < TOPK; k++) {
        float v; int e;
        if (a0 >= a1) { v = a0; e = lane; } else { v = a1; e = lane + 32; }
        #pragma unroll
        for (int o = 16; o; o >>= 1) {
            float ov = __shfl_xor_sync(0xffffffffu, v, o);
            int   oe = __shfl_xor_sync(0xffffffffu, e, o);
            if (ov > v || (ov == v && oe < e)) { v = ov; e = oe; }
        }
        if (e == lane)      a0 = -1e30f;
        if (e == lane + 32) a1 = -1e30f;
        float ra = __shfl_sync(0xffffffffu, r0, e & 31);
        float rb = __shfl_sync(0xffffffffu, r1, e & 31);
        float rs = (e < 32) ? ra : rb;
        sel_e[k] = e; sel_r[k] = rs; sum += rs;
    }
    float inv = 1.f / sum;
    if (lane < TOPK) {
        g_idx[t * TOPK + lane] = sel_e[lane];
        g_wk [t * TOPK + lane] = sel_r[lane] * inv;
        atomicAdd(&g_cnt[sel_e[lane]], 1);
    }
}

// ---------------- kernel 4: scan ----------------
__global__ void k_scan() {
    if (threadIdx.x == 0) {
        int acc = 0;
        for (int i = 0; i < NGRP; i++) {
            g_off[i] = acc;
            if (i < ER) g_fill[i] = acc;
            acc += g_cnt[i];
        }
        g_off[NGRP] = acc;
    }
}

// ---------------- kernel 5: scatter ----------------
__global__ void k_scatter() {
    int p = blockIdx.x * 256 + threadIdx.x;
    if (p >= NPAIR) return;
    if (p < NPAIR_R) {
        int t = p / TOPK, k = p % TOPK;
        int e = g_idx[p];
        int pos = atomicAdd(&g_fill[e], 1);
        g_ptok[pos] = t;
        g_pw  [pos] = g_wk[p];
        g_pos[t * 8 + k] = pos;
    } else {
        int q = p - NPAIR_R;
        int j = q / T_TOK, t = q % T_TOK;
        g_ptok[p] = t;
        g_pw  [p] = 1.0f;
        g_pos[t * 8 + TOPK + j] = p;
    }
}

// ================= bf16 tensor-core GEMM =================
// BM=128, BN=64, BK=32, 256 threads = 8 warps (4 m x 2 n), warp tile 32x32.
#define AST 20   // uint32 stride per A row (16 used + pad) -> conflict-free frags
#define BST 72   // uint32 stride per B k-pair row

// compute one BK=32 chunk from smem buffers
__device__ __forceinline__ void tile_mma(const uint32_t* __restrict__ Ab,
                                         const uint32_t* __restrict__ Bb,
                                         float acc[2][4][4],
                                         int row0, int warp_n, int gid, int tig) {
    #pragma unroll
    for (int ks = 0; ks < 2; ks++) {
        int base = ks * 8;
        #pragma unroll
        for (int s = 0; s < 2; s++) {
            int ra = (row0 + s * 16) * AST;
            uint32_t a0 = Ab[ra + base + tig];
            uint32_t a1 = Ab[ra + 8 * AST + base + tig];
            uint32_t a2 = Ab[ra + base + 4 + tig];
            uint32_t a3 = Ab[ra + 8 * AST + base + 4 + tig];
            #pragma unroll
            for (int nt = 0; nt < 4; nt++) {
                int nc = warp_n * 32 + nt * 8 + gid;
                uint32_t b0 = Bb[(base + tig) * BST + nc];
                uint32_t b1 = Bb[(base + 4 + tig) * BST + nc];
                mma_bf16(acc[s][nt], a0, a1, a2, a3, b0, b1);
            }
        }
    }
}

// ---------------- kernel 6: grouped GEMM1 h = gather(xn) @ W1[e] + b1 --------
__global__ void __launch_bounds__(256) k_gemm1(const float* __restrict__ rW1,
                                               const float* __restrict__ sW1,
                                               const float* __restrict__ rb1,
                                               const float* __restrict__ sb1) {
    __shared__ uint32_t As[2][128 * AST];
    __shared__ uint32_t Bs[2][16 * BST];
    __shared__ const float* Arow[128];
    int grp = blockIdx.z;
    int start = g_off[grp];
    int cnt = g_off[grp + 1] - start;
    const float* B    = (grp < ER) ? rW1 + (size_t)grp * DM * HM
                                   : sW1 + (size_t)(grp - ER) * DM * HM;
    const float* bias = (grp < ER) ? rb1 + (size_t)grp * HM
                                   : sb1 + (size_t)(grp - ER) * HM;
    int nb = blockIdx.y * 64;
    int tid = threadIdx.x, lane = tid & 31, wid = tid >> 5;
    int warp_m = wid >> 1, warp_n = wid & 1;
    int gid = lane >> 2, tig = lane & 3;
    int row0 = warp_m * 32 + gid;
    int am[4], akv[4];
    #pragma unroll
    for (int l = 0; l < 4; l++) { int idx = tid + l * 256; am[l] = idx >> 3; akv[l] = idx & 7; }
    int bkw = tid >> 4, bnv = tid & 15;

    for (int mt = blockIdx.x; mt * 128 < cnt; mt += gridDim.x) {
        int m0 = mt * 128;
        int rem = cnt - m0; if (rem > 128) rem = 128;
        __syncthreads();
        if (tid < 128)
            Arow[tid] = (tid < rem) ? g_xn + (size_t)g_ptok[start + m0 + tid] * DM : g_xn;
        __syncthreads();
        float acc[2][4][4];
        #pragma unroll
        for (int s = 0; s < 2; s++)
            #pragma unroll
            for (int n = 0; n < 4; n++)
                #pragma unroll
                for (int j = 0; j < 4; j++) acc[s][n][j] = 0.f;
        float4 aR[4], bR0, bR1;
        #pragma unroll
        for (int l = 0; l < 4; l++) aR[l] = *(const float4*)(Arow[am[l]] + akv[l] * 4);
        { const float* bp = B + (size_t)(2 * bkw) * HM + nb + bnv * 4;
          bR0 = *(const float4*)bp; bR1 = *(const float4*)(bp + HM); }
        #pragma unroll
        for (int l = 0; l < 4; l++) {
            uint32_t* d = &As[0][am[l] * AST + akv[l] * 2];
            d[0] = pk(aR[l].x, aR[l].y); d[1] = pk(aR[l].z, aR[l].w);
        }
        { uint32_t* d = &Bs[0][bkw * BST + bnv * 4];
          d[0] = pk(bR0.x, bR1.x); d[1] = pk(bR0.y, bR1.y);
          d[2] = pk(bR0.z, bR1.z); d[3] = pk(bR0.w, bR1.w); }
        __syncthreads();
        int buf = 0;
        for (int kk = 0; kk < DM; kk += 32) {
            int nxt = kk + 32;
            if (nxt < DM) {
                #pragma unroll
                for (int l = 0; l < 4; l++)
                    aR[l] = *(const float4*)(Arow[am[l]] + nxt + akv[l] * 4);
                const float* bp = B + (size_t)(nxt + 2 * bkw) * HM + nb + bnv * 4;
                bR0 = *(const float4*)bp; bR1 = *(const float4*)(bp + HM);
            }
            tile_mma(As[buf], Bs[buf], acc, row0, warp_n, gid, tig);
            if (nxt < DM) {
                #pragma unroll
                for (int l = 0; l < 4; l++) {
                    uint32_t* d = &As[buf ^ 1][am[l] * AST + akv[l] * 2];
                    d[0] = pk(aR[l].x, aR[l].y); d[1] = pk(aR[l].z, aR[l].w);
                }
                uint32_t* d = &Bs[buf ^ 1][bkw * BST + bnv * 4];
                d[0] = pk(bR0.x, bR1.x); d[1] = pk(bR0.y, bR1.y);
                d[2] = pk(bR0.z, bR1.z); d[3] = pk(bR0.w, bR1.w);
            }
            buf ^= 1;
            __syncthreads();
        }
        #pragma unroll
        for (int s = 0; s < 2; s++) {
            int rA = row0 + s * 16;
            #pragma unroll
            for (int nt = 0; nt < 4; nt++) {
                int col = nb + warp_n * 32 + nt * 8 + 2 * tig;
                float2 bv = *(const float2*)&bias[col];
                if (rA < rem) {
                    int p = start + m0 + rA;
                    *(float2*)&g_h[(size_t)p * HM + col] =
                        make_float2(acc[s][nt][0] + bv.x, acc[s][nt][1] + bv.y);
                }
                if (rA + 8 < rem) {
                    int p = start + m0 + rA + 8;
                    *(float2*)&g_h[(size_t)p * HM + col] =
                        make_float2(acc[s][nt][2] + bv.x, acc[s][nt][3] + bv.y);
                }
            }
        }
    }
}

// ---------------- kernel 7: gate  g = silu(h @ Wg) * h ----------------
__global__ void __launch_bounds__(256) k_gate(const float* __restrict__ rWg,
                                              const float* __restrict__ sWg) {
    __shared__ uint32_t As[2][128 * AST];
    __shared__ uint32_t Bs[2][16 * BST];
    int p0 = blockIdx.x * 128;
    const float* B = (p0 < NPAIR_R) ? rWg : sWg;
    int nb = blockIdx.y * 64;
    int tid = threadIdx.x, lane = tid & 31, wid = tid >> 5;
    int warp_m = wid >> 1, warp_n = wid & 1;
    int gid = lane >> 2, tig = lane & 3;
    int row0 = warp_m * 32 + gid;
    int am[4], akv[4];
    #pragma unroll
    for (int l = 0; l < 4; l++) { int idx = tid + l * 256; am[l] = idx >> 3; akv[l] = idx & 7; }
    int bkw = tid >> 4, bnv = tid & 15;
    const float* Abase = g_h + (size_t)p0 * HM;

    float acc[2][4][4];
    #pragma unroll
    for (int s = 0; s < 2; s++)
        #pragma unroll
        for (int n = 0; n < 4; n++)
            #pragma unroll
            for (int j = 0; j < 4; j++) acc[s][n][j] = 0.f;
    float4 aR[4], bR0, bR1;
    #pragma unroll
    for (int l = 0; l < 4; l++)
        aR[l] = *(const float4*)(Abase + (size_t)am[l] * HM + akv[l] * 4);
    { const float* bp = B + (size_t)(2 * bkw) * HM + nb + bnv * 4;
      bR0 = *(const float4*)bp; bR1 = *(const float4*)(bp + HM); }
    #pragma unroll
    for (int l = 0; l < 4; l++) {
        uint32_t* d = &As[0][am[l] * AST + akv[l] * 2];
        d[0] = pk(aR[l].x, aR[l].y); d[1] = pk(aR[l].z, aR[l].w);
    }
    { uint32_t* d = &Bs[0][bkw * BST + bnv * 4];
      d[0] = pk(bR0.x, bR1.x); d[1] = pk(bR0.y, bR1.y);
      d[2] = pk(bR0.z, bR1.z); d[3] = pk(bR0.w, bR1.w); }
    __syncthreads();
    int buf = 0;
    for (int kk = 0; kk < HM; kk += 32) {
        int nxt = kk + 32;
        if (nxt < HM) {
            #pragma unroll
            for (int l = 0; l < 4; l++)
                aR[l] = *(const float4*)(Abase + (size_t)am[l] * HM + nxt + akv[l] * 4);
            const float* bp = B + (size_t)(nxt + 2 * bkw) * HM + nb + bnv * 4;
            bR0 = *(const float4*)bp; bR1 = *(const float4*)(bp + HM);
        }
        tile_mma(As[buf], Bs[buf], acc, row0, warp_n, gid, tig);
        if (nxt < HM) {
            #pragma unroll
            for (int l = 0; l < 4; l++) {
                uint32_t* d = &As[buf ^ 1][am[l] * AST + akv[l] * 2];
                d[0] = pk(aR[l].x, aR[l].y); d[1] = pk(aR[l].z, aR[l].w);
            }
            uint32_t* d = &Bs[buf ^ 1][bkw * BST + bnv * 4];
            d[0] = pk(bR0.x, bR1.x); d[1] = pk(bR0.y, bR1.y);
            d[2] = pk(bR0.z, bR1.z); d[3] = pk(bR0.w, bR1.w);
        }
        buf ^= 1;
        __syncthreads();
    }
    #pragma unroll
    for (int s = 0; s < 2; s++) {
        int rA = row0 + s * 16;
        #pragma unroll
        for (int nt = 0; nt < 4; nt++) {
            int col = nb + warp_n * 32 + nt * 8 + 2 * tig;
            {
                size_t base = (size_t)(p0 + rA) * HM + col;
                float2 h2 = *(float2*)&g_h[base];
                float2 r;
                float v0 = acc[s][nt][0], v1 = acc[s][nt][1];
                r.x = (v0 / (1.f + __expf(-v0))) * h2.x;
                r.y = (v1 / (1.f + __expf(-v1))) * h2.y;
                *(float2*)&g_g[base] = r;
            }
            {
                size_t base = (size_t)(p0 + rA + 8) * HM + col;
                float2 h2 = *(float2*)&g_h[base];
                float2 r;
                float v2 = acc[s][nt][2], v3 = acc[s][nt][3];
                r.x = (v2 / (1.f + __expf(-v2))) * h2.x;
                r.y = (v3 / (1.f + __expf(-v3))) * h2.y;
                *(float2*)&g_g[base] = r;
            }
        }
    }
}

// ---------------- kernel 8: grouped GEMM2 po = (g @ W2[e] + b2) * w ----------
__global__ void __launch_bounds__(256) k_gemm2(const float* __restrict__ rW2,
                                               const float* __restrict__ sW2,
                                               const float* __restrict__ rb2,
                                               const float* __restrict__ sb2) {
    __shared__ uint32_t As[2][128 * AST];
    __shared__ uint32_t Bs[2][16 * BST];
    __shared__ float Pw[128];
    int grp = blockIdx.z;
    int start = g_off[grp];
    int cnt = g_off[grp + 1] - start;
    const float* B  = (grp < ER) ? rW2 + (size_t)grp * HM * DM
                                 : sW2 + (size_t)(grp - ER) * HM * DM;
    const float* b2 = (grp < ER) ? rb2 + (size_t)grp * DM
                                 : sb2 + (size_t)(grp - ER) * DM;
    int nb = blockIdx.y * 64;
    int tid = threadIdx.x, lane = tid & 31, wid = tid >> 5;
    int warp_m = wid >> 1, warp_n = wid & 1;
    int gid = lane >> 2, tig = lane & 3;
    int row0 = warp_m * 32 + gid;
    int am[4], akv[4];
    #pragma unroll
    for (int l = 0; l < 4; l++) { int idx = tid + l * 256; am[l] = idx >> 3; akv[l] = idx & 7; }
    int bkw = tid >> 4, bnv = tid & 15;

    for (int mt = blockIdx.x; mt * 128 < cnt; mt += gridDim.x) {
        int m0 = mt * 128;
        int rem = cnt - m0; if (rem > 128) rem = 128;
        __syncthreads();
        if (tid < 128 && tid < rem) Pw[tid] = g_pw[start + m0 + tid];
        __syncthreads();
        const float* Abase = g_g + (size_t)(start + m0) * HM;
        float acc[2][4][4];
        #pragma unroll
        for (int s = 0; s < 2; s++)
            #pragma unroll
            for (int n = 0; n < 4; n++)
                #pragma unroll
                for (int j = 0; j < 4; j++) acc[s][n][j] = 0.f;
        float4 aR[4], bR0, bR1;
        #pragma unroll
        for (int l = 0; l < 4; l++)
            aR[l] = *(const float4*)(Abase + (size_t)am[l] * HM + akv[l] * 4);
        { const float* bp = B + (size_t)(2 * bkw) * DM + nb + bnv * 4;
          bR0 = *(const float4*)bp; bR1 = *(const float4*)(bp + DM); }
        #pragma unroll
        for (int l = 0; l < 4; l++) {
            uint32_t* d = &As[0][am[l] * AST + akv[l] * 2];
            d[0] = pk(aR[l].x, aR[l].y); d[1] = pk(aR[l].z, aR[l].w);
        }
        { uint32_t* d = &Bs[0][bkw * BST + bnv * 4];
          d[0] = pk(bR0.x, bR1.x); d[1] = pk(bR0.y, bR1.y);
          d[2] = pk(bR0.z, bR1.z); d[3] = pk(bR0.w, bR1.w); }
        __syncthreads();
        int buf = 0;
        for (int kk = 0; kk < HM; kk += 32) {
            int nxt = kk + 32;
            if (nxt < HM) {
                #pragma unroll
                for (int l = 0; l < 4; l++)
                    aR[l] = *(const float4*)(Abase + (size_t)am[l] * HM + nxt + akv[l] * 4);
                const float* bp = B + (size_t)(nxt + 2 * bkw) * DM + nb + bnv * 4;
                bR0 = *(const float4*)bp; bR1 = *(const float4*)(bp + DM);
            }
            tile_mma(As[buf], Bs[buf], acc, row0, warp_n, gid, tig);
            if (nxt < HM) {
                #pragma unroll
                for (int l = 0; l < 4; l++) {
                    uint32_t* d = &As[buf ^ 1][am[l] * AST + akv[l] * 2];
                    d[0] = pk(aR[l].x, aR[l].y); d[1] = pk(aR[l].z, aR[l].w);
                }
                uint32_t* d = &Bs[buf ^ 1][bkw * BST + bnv * 4];
                d[0] = pk(bR0.x, bR1.x); d[1] = pk(bR0.y, bR1.y);
                d[2] = pk(bR0.z, bR1.z); d[3] = pk(bR0.w, bR1.w);
            }
            buf ^= 1;
            __syncthreads();
        }
        #pragma unroll
        for (int s = 0; s < 2; s++) {
            int rA = row0 + s * 16;
            #pragma unroll
            for (int nt = 0; nt < 4; nt++) {
                int col = nb + warp_n * 32 + nt * 8 + 2 * tig;
                float2 bv = *(const float2*)&b2[col];
                if (rA < rem) {
                    int p = start + m0 + rA;
                    float w = Pw[rA];
                    *(float2*)&g_po[(size_t)p * DM + col] =
                        make_float2((acc[s][nt][0] + bv.x) * w, (acc[s][nt][1] + bv.y) * w);
                }
                if (rA + 8 < rem) {
                    int p = start + m0 + rA + 8;
                    float w = Pw[rA + 8];
                    *(float2*)&g_po[(size_t)p * DM + col] =
                        make_float2((acc[s][nt][2] + bv.x) * w, (acc[s][nt][3] + bv.y) * w);
                }
            }
        }
    }
}

// ---------------- kernel 9: per-token reduce of 8 pair rows ----------------
__global__ void __launch_bounds__(256) k_reduce(float* __restrict__ out) {
    int t = blockIdx.x, tid = threadIdx.x;
    __shared__ int pos[8];
    if (tid < 8) pos[tid] = g_pos[t * 8 + tid];
    __syncthreads();
    size_t d0 = (size_t)tid * 4;
    float4 s = *(float4*)&out[(size_t)t * DM + d0];
    #pragma unroll
    for (int j = 0; j < 8; j++) {
        float4 v = *(const float4*)&g_po[(size_t)pos[j] * DM + d0];
        s.x += v.x; s.y += v.y; s.z += v.z; s.w += v.w;
    }
    *(float4*)&out[(size_t)t * DM + d0] = s;
}

// ---------------- launcher ----------------
extern "C" void kernel_launch(void* const* d_in, const int* in_sizes, int n_in,
                              void* d_out, int out_size) {
    const float* x      = (const float*)d_in[0];
    const float* norm_w = (const float*)d_in[1];
    const float* Wr     = (const float*)d_in[2];
    const float* sW1    = (const float*)d_in[3];
    const float* sb1    = (const float*)d_in[4];
    const float* sW2    = (const float*)d_in[5];
    const float* sb2    = (const float*)d_in[6];
    const float* sWg    = (const float*)d_in[7];
    const float* rW1    = (const float*)d_in[8];
    const float* rb1    = (const float*)d_in[9];
    const float* rW2    = (const float*)d_in[10];
    const float* rb2    = (const float*)d_in[11];
    const float* rWg    = (const float*)d_in[12];
    const float* bias   = (const float*)d_in[13];
    float* out = (float*)d_out;

    k_zero<<<1, 128>>>();
    k_rmsnorm<<<T_TOK, 256>>>(x, norm_w, out);
    k_raw<<<T_TOK / 64, 256>>>(Wr);
    k_topk<<<T_TOK / 8, 256>>>(bias);
    k_scan<<<1, 32>>>();
    k_scatter<<<(NPAIR + 255) / 256, 256>>>();
    k_gemm1<<<dim3(2, HM / 64, NGRP), 256>>>(rW1, sW1, rb1, sb1);
    k_gate<<<dim3(NPAIR / 128, HM / 64), 256>>>(rWg, sWg);
    k_gemm2<<<dim3(2, DM / 64, NGRP), 256>>>(rW2, sW2, rb2, sb2);
    k_reduce<<<T_TOK, 256>>>(out);
}

// round 5
// speedup vs baseline: 5.1113x; 1.4977x over previous
#include <cuda_runtime.h>
#include <math.h>
#include <stdint.h>

// ---------------- problem constants ----------------
#define T_TOK   2048
#define DM      1024
#define HM      512
#define ER      64
#define TOPK    6
#define ES      2
#define NGRP    (ER + ES)
#define NPAIR_R (T_TOK * TOPK)
#define NPAIR   (NPAIR_R + T_TOK * ES)
#define EPSR    1.1920929e-07f

// ---------------- GEMM tile config ----------------
#define BMG   256                 // block M
#define BNG   128                 // block N
#define BK    32                  // block K
#define AST   20                  // uint32 stride per A row (16 data + 4 pad)
#define BST   68                  // uint32 stride per B k-row (64 data + 4 pad)
#define ABUFW (BMG * AST)         // 5120 uint32 per A buffer
#define BBUFW (BK * BST)          // 2176 uint32 per B buffer
#define ABUF_BYTES (ABUFW * 4)    // 20480
#define BBUF_BYTES (BBUFW * 4)    // 8704
#define BOFF  (2 * ABUF_BYTES)    // 40960
#define XOFF  (BOFF + 2 * BBUF_BYTES) // 58368 (sArow / sPw region)
#define DSMEM (XOFF + 2048)       // 60416 bytes dynamic smem

// ---------------- device scratch ----------------
__device__ float    g_xn [T_TOK * DM];              // fp32 normed (router only)
__device__ uint32_t g_xnb[T_TOK * DM / 2];          // bf16x2 normed tokens
__device__ float    g_raw[T_TOK * ER];
__device__ int      g_idx[T_TOK * TOPK];
__device__ float    g_wk [T_TOK * TOPK];
__device__ int      g_cnt[NGRP];
__device__ int      g_off[NGRP + 1];
__device__ int      g_fill[ER];
__device__ int      g_ptok[NPAIR];
__device__ float    g_pw  [NPAIR];
__device__ int      g_pos [T_TOK * 8];
__device__ uint32_t g_hb  [(size_t)NPAIR * HM / 2]; // bf16x2 hidden
__device__ uint32_t g_gb  [(size_t)NPAIR * HM / 2]; // bf16x2 gated hidden
__device__ float    g_po  [(size_t)NPAIR * DM];     // fp32 per-pair outputs

// ---------------- PTX helpers ----------------
__device__ __forceinline__ uint32_t pk(float lo, float hi) {
    uint32_t r;
    asm("cvt.rn.bf16x2.f32 %0, %1, %2;" : "=r"(r) : "f"(hi), "f"(lo));
    return r;
}
__device__ __forceinline__ uint32_t cvta(const void* p) {
    return (uint32_t)__cvta_generic_to_shared(p);
}
__device__ __forceinline__ void mma_bf16(float* c, uint32_t a0, uint32_t a1,
                                         uint32_t a2, uint32_t a3,
                                         uint32_t b0, uint32_t b1) {
    asm volatile(
        "mma.sync.aligned.m16n8k16.row.col.f32.bf16.bf16.f32 "
        "{%0,%1,%2,%3}, {%4,%5,%6,%7}, {%8,%9}, {%0,%1,%2,%3};\n"
        : "+f"(c[0]), "+f"(c[1]), "+f"(c[2]), "+f"(c[3])
        : "r"(a0), "r"(a1), "r"(a2), "r"(a3), "r"(b0), "r"(b1));
}
__device__ __forceinline__ void ldsm4(uint32_t& r0, uint32_t& r1, uint32_t& r2,
                                      uint32_t& r3, uint32_t a) {
    asm volatile("ldmatrix.sync.aligned.m8n8.x4.shared.b16 {%0,%1,%2,%3}, [%4];"
                 : "=r"(r0), "=r"(r1), "=r"(r2), "=r"(r3) : "r"(a));
}
__device__ __forceinline__ void ldsm4t(uint32_t& r0, uint32_t& r1, uint32_t& r2,
                                       uint32_t& r3, uint32_t a) {
    asm volatile("ldmatrix.sync.aligned.m8n8.x4.trans.shared.b16 {%0,%1,%2,%3}, [%4];"
                 : "=r"(r0), "=r"(r1), "=r"(r2), "=r"(r3) : "r"(a));
}
#define CPA(dst, src) \
    asm volatile("cp.async.ca.shared.global [%0], [%1], 16;" \
                 :: "r"(dst), "l"(src) : "memory")
#define CPC() asm volatile("cp.async.commit_group;" ::: "memory")
#define CPW() asm volatile("cp.async.wait_group 0;" ::: "memory")

// ---------------- kernel 0 ----------------
__global__ void k_zero() {
    int i = threadIdx.x;
    if (i < NGRP) g_cnt[i] = (i < ER) ? 0 : T_TOK;
}

// ---------------- kernel 1: RMSNorm + residual init ----------------
__global__ void __launch_bounds__(256) k_rmsnorm(const float* __restrict__ x,
                                                 const float* __restrict__ nw,
                                                 float* __restrict__ out) {
    int t = blockIdx.x, tid = threadIdx.x;
    const float4* xr = (const float4*)(x + (size_t)t * DM);
    float4 a = xr[tid];
    float s = a.x * a.x + a.y * a.y + a.z * a.z + a.w * a.w;
    #pragma unroll
    for (int o = 16; o; o >>= 1) s += __shfl_xor_sync(0xffffffffu, s, o);
    __shared__ float ws[8];
    __shared__ float s_scale;
    if ((tid & 31) == 0) ws[tid >> 5] = s;
    __syncthreads();
    if (tid == 0) {
        float tot = 0.f;
        #pragma unroll
        for (int i = 0; i < 8; i++) tot += ws[i];
        s_scale = rsqrtf(tot / (float)DM + EPSR);
    }
    __syncthreads();
    float sc = s_scale;
    float4 w4 = ((const float4*)nw)[tid];
    float4 r;
    r.x = a.x * sc * w4.x; r.y = a.y * sc * w4.y;
    r.z = a.z * sc * w4.z; r.w = a.w * sc * w4.w;
    ((float4*)g_xn)[(size_t)t * 256 + tid] = r;
    ((uint2*)g_xnb)[(size_t)t * 256 + tid] = make_uint2(pk(r.x, r.y), pk(r.z, r.w));
    ((float4*)out)[(size_t)t * 256 + tid]  = a;
}

// ---------------- kernel 2: router raw affinities (fp32, bit-safe) ----------
#define RPAD 68
__global__ void __launch_bounds__(256) k_raw(const float* __restrict__ Wr) {
    __shared__ float As[16][RPAD];
    __shared__ float Bs[16][RPAD];
    int t0 = blockIdx.x * 64;
    int tid = threadIdx.x, tx = tid & 15, ty = tid >> 4;
    float acc[4][4];
    #pragma unroll
    for (int i = 0; i < 4; i++)
        #pragma unroll
        for (int j = 0; j < 4; j++) acc[i][j] = 0.f;
    int m = tid >> 2, kv = tid & 3;
    for (int kk = 0; kk < DM; kk += 16) {
        float4 av = *(const float4*)(g_xn + (size_t)(t0 + m) * DM + kk + kv * 4);
        float4 bv = *(const float4*)(Wr + (size_t)m * DM + kk + kv * 4);
        As[kv * 4 + 0][m] = av.x; As[kv * 4 + 1][m] = av.y;
        As[kv * 4 + 2][m] = av.z; As[kv * 4 + 3][m] = av.w;
        Bs[kv * 4 + 0][m] = bv.x; Bs[kv * 4 + 1][m] = bv.y;
        Bs[kv * 4 + 2][m] = bv.z; Bs[kv * 4 + 3][m] = bv.w;
        __syncthreads();
        #pragma unroll
        for (int k = 0; k < 16; k++) {
            float4 a4 = *(float4*)&As[k][ty * 4];
            float4 b4 = *(float4*)&Bs[k][tx * 4];
            float aa[4] = {a4.x, a4.y, a4.z, a4.w};
            float bb[4] = {b4.x, b4.y, b4.z, b4.w};
            #pragma unroll
            for (int i = 0; i < 4; i++)
                #pragma unroll
                for (int j = 0; j < 4; j++) acc[i][j] += aa[i] * bb[j];
        }
        __syncthreads();
    }
    #pragma unroll
    for (int i = 0; i < 4; i++)
        #pragma unroll
        for (int j = 0; j < 4; j++)
            g_raw[(size_t)(t0 + ty * 4 + i) * ER + tx * 4 + j] = acc[i][j];
}

// ---------------- kernel 3: top-6 per token ----------------
__global__ void __launch_bounds__(256) k_topk(const float* __restrict__ bias) {
    int tid = threadIdx.x, lane = tid & 31, wid = tid >> 5;
    int t = blockIdx.x * 8 + wid;
    float r0 = g_raw[(size_t)t * ER + lane];
    float r1 = g_raw[(size_t)t * ER + lane + 32];
    float a0 = r0 + bias[lane];
    float a1 = r1 + bias[lane + 32];
    float sum = 0.f;
    int   sel_e[TOPK];
    float sel_r[TOPK];
    #pragma unroll
    for (int k = 0; k < TOPK; k++) {
        float v; int e;
        if (a0 >= a1) { v = a0; e = lane; } else { v = a1; e = lane + 32; }
        #pragma unroll
        for (int o = 16; o; o >>= 1) {
            float ov = __shfl_xor_sync(0xffffffffu, v, o);
            int   oe = __shfl_xor_sync(0xffffffffu, e, o);
            if (ov > v || (ov == v && oe < e)) { v = ov; e = oe; }
        }
        if (e == lane)      a0 = -1e30f;
        if (e == lane + 32) a1 = -1e30f;
        float ra = __shfl_sync(0xffffffffu, r0, e & 31);
        float rb = __shfl_sync(0xffffffffu, r1, e & 31);
        float rs = (e < 32) ? ra : rb;
        sel_e[k] = e; sel_r[k] = rs; sum += rs;
    }
    float inv = 1.f / sum;
    if (lane < TOPK) {
        g_idx[t * TOPK + lane] = sel_e[lane];
        g_wk [t * TOPK + lane] = sel_r[lane] * inv;
        atomicAdd(&g_cnt[sel_e[lane]], 1);
    }
}

// ---------------- kernel 4: scan ----------------
__global__ void k_scan() {
    if (threadIdx.x == 0) {
        int acc = 0;
        for (int i = 0; i < NGRP; i++) {
            g_off[i] = acc;
            if (i < ER) g_fill[i] = acc;
            acc += g_cnt[i];
        }
        g_off[NGRP] = acc;
    }
}

// ---------------- kernel 5: scatter ----------------
__global__ void k_scatter() {
    int p = blockIdx.x * 256 + threadIdx.x;
    if (p >= NPAIR) return;
    if (p < NPAIR_R) {
        int t = p / TOPK, k = p % TOPK;
        int e = g_idx[p];
        int pos = atomicAdd(&g_fill[e], 1);
        g_ptok[pos] = t;
        g_pw  [pos] = g_wk[p];
        g_pos[t * 8 + k] = pos;
    } else {
        int q = p - NPAIR_R;
        int j = q / T_TOK, t = q % T_TOK;
        g_ptok[p] = t;
        g_pw  [p] = 1.0f;
        g_pos[t * 8 + TOPK + j] = p;
    }
}

// ================= GEMM core pieces =================
// per-chunk mma: warp tile 32x64 (2 m16 x 8 n8), BK=32 (2 ksteps of k16)
__device__ __forceinline__ void mma_chunk(uint32_t aA, uint32_t aB,
                                          float acc[2][8][4],
                                          int warp_m, int warp_n, int lane) {
    int sel = lane >> 3, li = lane & 7;
    int arow = (sel & 1) * 8 + li;        // row within m16 tile-set
    int acol = (sel >> 1) * 4;            // kpair offset 0/4
    int brow = (sel & 1) * 8 + li;        // k-row within k16
    int bn   = (sel >> 1) * 8;            // n offset 0/8 within n16 pair
    #pragma unroll
    for (int ks = 0; ks < 2; ks++) {
        uint32_t a[2][4];
        #pragma unroll
        for (int s = 0; s < 2; s++) {
            uint32_t addr = aA + (uint32_t)(((warp_m * 32 + s * 16 + arow) * AST
                                             + ks * 8 + acol) * 4);
            ldsm4(a[s][0], a[s][1], a[s][2], a[s][3], addr);
        }
        #pragma unroll
        for (int p = 0; p < 4; p++) {
            uint32_t b0, b1, b2, b3;
            uint32_t addr = aB + (uint32_t)((ks * 16 + brow) * (BST * 4)
                                            + (warp_n * 64 + p * 16 + bn) * 2);
            ldsm4t(b0, b1, b2, b3, addr);
            #pragma unroll
            for (int s = 0; s < 2; s++) {
                mma_bf16(acc[s][2 * p],     a[s][0], a[s][1], a[s][2], a[s][3], b0, b1);
                mma_bf16(acc[s][2 * p + 1], a[s][0], a[s][1], a[s][2], a[s][3], b2, b3);
            }
        }
    }
}

// B chunk: 32 k-rows x 128 n, fp32 gmem -> regs
__device__ __forceinline__ void ldB(const float* __restrict__ W, int ldb, int kk,
                                    int nb, int tid, float4& f0, float4& f1) {
    const float* p = W + (size_t)(kk + (tid >> 4)) * ldb + nb + (tid & 15) * 8;
    f0 = *(const float4*)p;
    f1 = *(const float4*)(p + 4);
}
__device__ __forceinline__ void stB(uint32_t* Bbase, int tid, float4 f0, float4 f1) {
    uint4 u = make_uint4(pk(f0.x, f0.y), pk(f0.z, f0.w),
                         pk(f1.x, f1.y), pk(f1.z, f1.w));
    *(uint4*)(Bbase + (tid >> 4) * BST + (tid & 15) * 4) = u;
}

// ---------------- kernel 6: grouped GEMM1 h = gather(xnb) @ W1[e] + b1 ------
__global__ void __launch_bounds__(512, 1)
k_gemm1(const float* __restrict__ rW1, const float* __restrict__ sW1,
        const float* __restrict__ rb1, const float* __restrict__ sb1) {
    extern __shared__ uint8_t dyn[];
    uint32_t* Ab = (uint32_t*)dyn;
    uint32_t* Bb = (uint32_t*)(dyn + BOFF);
    const uint32_t** sArow = (const uint32_t**)(dyn + XOFF);
    uint32_t saA = cvta(Ab), saB = cvta(Bb);
    int grp = blockIdx.z;
    int start = g_off[grp], cnt = g_off[grp + 1] - start;
    const float* W  = (grp < ER) ? rW1 + (size_t)grp * DM * HM
                                 : sW1 + (size_t)(grp - ER) * DM * HM;
    const float* bv = (grp < ER) ? rb1 + (size_t)grp * HM
                                 : sb1 + (size_t)(grp - ER) * HM;
    int nb = blockIdx.y * BNG;
    int tid = threadIdx.x, lane = tid & 31, wid = tid >> 5;
    int warp_m = wid >> 1, warp_n = wid & 1;
    int amf = tid >> 1, ahalf = tid & 1;

    for (int mt = blockIdx.x; mt * BMG < cnt; mt += gridDim.x) {
        int m0 = mt * BMG;
        int rem = cnt - m0; if (rem > BMG) rem = BMG;
        __syncthreads();
        if (tid < BMG)
            sArow[tid] = (tid < rem)
                ? g_xnb + (size_t)g_ptok[start + m0 + tid] * (DM / 2) : g_xnb;
        __syncthreads();
        float acc[2][8][4];
        #pragma unroll
        for (int s = 0; s < 2; s++)
            #pragma unroll
            for (int n = 0; n < 8; n++)
                #pragma unroll
                for (int j = 0; j < 4; j++) acc[s][n][j] = 0.f;
        // prologue
        {
            float4 f0, f1;
            ldB(W, HM, 0, nb, tid, f0, f1);
            stB(Bb, tid, f0, f1);
            uint32_t dst = saA + (uint32_t)((amf * AST + ahalf * 8) * 4);
            const uint32_t* src = sArow[amf] + ahalf * 8;
            CPA(dst, src); CPA(dst + 16, src + 4); CPC(); CPW();
        }
        __syncthreads();
        int buf = 0;
        for (int c = 0; c < DM / BK; c++) {
            float4 f0, f1;
            bool pre = (c + 1 < DM / BK);
            if (pre) {
                ldB(W, HM, (c + 1) * BK, nb, tid, f0, f1);
                uint32_t dst = saA + (buf ^ 1) * ABUF_BYTES
                             + (uint32_t)((amf * AST + ahalf * 8) * 4);
                const uint32_t* src = sArow[amf] + (c + 1) * 16 + ahalf * 8;
                CPA(dst, src); CPA(dst + 16, src + 4); CPC();
            }
            mma_chunk(saA + buf * ABUF_BYTES, saB + buf * BBUF_BYTES,
                      acc, warp_m, warp_n, lane);
            if (pre) stB(Bb + (buf ^ 1) * BBUFW, tid, f0, f1);
            CPW();
            __syncthreads();
            buf ^= 1;
        }
        // epilogue: +bias, pack bf16 to g_hb
        #pragma unroll
        for (int s = 0; s < 2; s++) {
            int mrow = warp_m * 32 + s * 16 + (lane >> 2);
            #pragma unroll
            for (int nt = 0; nt < 8; nt++) {
                int col = nb + warp_n * 64 + nt * 8 + (lane & 3) * 2;
                float2 bb = *(const float2*)&bv[col];
                if (mrow < rem) {
                    size_t p = (size_t)(start + m0 + mrow);
                    g_hb[(p * HM + col) >> 1] =
                        pk(acc[s][nt][0] + bb.x, acc[s][nt][1] + bb.y);
                }
                if (mrow + 8 < rem) {
                    size_t p = (size_t)(start + m0 + mrow + 8);
                    g_hb[(p * HM + col) >> 1] =
                        pk(acc[s][nt][2] + bb.x, acc[s][nt][3] + bb.y);
                }
            }
        }
    }
}

// ---------------- kernel 7: gate  g = silu(h @ Wg) * h ----------------
__global__ void __launch_bounds__(512, 1)
k_gate(const float* __restrict__ rWg, const float* __restrict__ sWg) {
    extern __shared__ uint8_t dyn[];
    uint32_t* Ab = (uint32_t*)dyn;
    uint32_t* Bb = (uint32_t*)(dyn + BOFF);
    uint32_t saA = cvta(Ab), saB = cvta(Bb);
    int p0 = blockIdx.x * BMG;
    const float* W = (p0 < NPAIR_R) ? rWg : sWg;
    int nb = blockIdx.y * BNG;
    int tid = threadIdx.x, lane = tid & 31, wid = tid >> 5;
    int warp_m = wid >> 1, warp_n = wid & 1;
    int amf = tid >> 1, ahalf = tid & 1;
    const uint32_t* arow = g_hb + (size_t)(p0 + amf) * (HM / 2);

    float acc[2][8][4];
    #pragma unroll
    for (int s = 0; s < 2; s++)
        #pragma unroll
        for (int n = 0; n < 8; n++)
            #pragma unroll
            for (int j = 0; j < 4; j++) acc[s][n][j] = 0.f;
    {
        float4 f0, f1;
        ldB(W, HM, 0, nb, tid, f0, f1);
        stB(Bb, tid, f0, f1);
        uint32_t dst = saA + (uint32_t)((amf * AST + ahalf * 8) * 4);
        const uint32_t* src = arow + ahalf * 8;
        CPA(dst, src); CPA(dst + 16, src + 4); CPC(); CPW();
    }
    __syncthreads();
    int buf = 0;
    for (int c = 0; c < HM / BK; c++) {
        float4 f0, f1;
        bool pre = (c + 1 < HM / BK);
        if (pre) {
            ldB(W, HM, (c + 1) * BK, nb, tid, f0, f1);
            uint32_t dst = saA + (buf ^ 1) * ABUF_BYTES
                         + (uint32_t)((amf * AST + ahalf * 8) * 4);
            const uint32_t* src = arow + (c + 1) * 16 + ahalf * 8;
            CPA(dst, src); CPA(dst + 16, src + 4); CPC();
        }
        mma_chunk(saA + buf * ABUF_BYTES, saB + buf * BBUF_BYTES,
                  acc, warp_m, warp_n, lane);
        if (pre) stB(Bb + (buf ^ 1) * BBUFW, tid, f0, f1);
        CPW();
        __syncthreads();
        buf ^= 1;
    }
    #pragma unroll
    for (int s = 0; s < 2; s++) {
        int mrow = warp_m * 32 + s * 16 + (lane >> 2);
        #pragma unroll
        for (int nt = 0; nt < 8; nt++) {
            int col = nb + warp_n * 64 + nt * 8 + (lane & 3) * 2;
            #pragma unroll
            for (int hh = 0; hh < 2; hh++) {
                size_t p = (size_t)(p0 + mrow + hh * 8);
                size_t idx = (p * HM + col) >> 1;
                uint32_t hu = g_hb[idx];
                float h0 = __uint_as_float(hu << 16);
                float h1 = __uint_as_float(hu & 0xffff0000u);
                float v0 = acc[s][nt][hh * 2 + 0];
                float v1 = acc[s][nt][hh * 2 + 1];
                float r0 = (v0 / (1.f + __expf(-v0))) * h0;
                float r1 = (v1 / (1.f + __expf(-v1))) * h1;
                g_gb[idx] = pk(r0, r1);
            }
        }
    }
}

// ---------------- kernel 8: grouped GEMM2 po = (g @ W2[e] + b2) * w ----------
__global__ void __launch_bounds__(512, 1)
k_gemm2(const float* __restrict__ rW2, const float* __restrict__ sW2,
        const float* __restrict__ rb2, const float* __restrict__ sb2) {
    extern __shared__ uint8_t dyn[];
    uint32_t* Ab = (uint32_t*)dyn;
    uint32_t* Bb = (uint32_t*)(dyn + BOFF);
    float* sPw = (float*)(dyn + XOFF);
    uint32_t saA = cvta(Ab), saB = cvta(Bb);
    int grp = blockIdx.z;
    int start = g_off[grp], cnt = g_off[grp + 1] - start;
    const float* W  = (grp < ER) ? rW2 + (size_t)grp * HM * DM
                                 : sW2 + (size_t)(grp - ER) * HM * DM;
    const float* bv = (grp < ER) ? rb2 + (size_t)grp * DM
                                 : sb2 + (size_t)(grp - ER) * DM;
    int nb = blockIdx.y * BNG;
    int tid = threadIdx.x, lane = tid & 31, wid = tid >> 5;
    int warp_m = wid >> 1, warp_n = wid & 1;
    int amf = tid >> 1, ahalf = tid & 1;

    for (int mt = blockIdx.x; mt * BMG < cnt; mt += gridDim.x) {
        int m0 = mt * BMG;
        int rem = cnt - m0; if (rem > BMG) rem = BMG;
        __syncthreads();
        if (tid < BMG) sPw[tid] = (tid < rem) ? g_pw[start + m0 + tid] : 0.f;
        __syncthreads();
        int ar = amf < rem ? amf : (rem - 1);
        const uint32_t* arow = g_gb + (size_t)(start + m0 + ar) * (HM / 2);
        float acc[2][8][4];
        #pragma unroll
        for (int s = 0; s < 2; s++)
            #pragma unroll
            for (int n = 0; n < 8; n++)
                #pragma unroll
                for (int j = 0; j < 4; j++) acc[s][n][j] = 0.f;
        {
            float4 f0, f1;
            ldB(W, DM, 0, nb, tid, f0, f1);
            stB(Bb, tid, f0, f1);
            uint32_t dst = saA + (uint32_t)((amf * AST + ahalf * 8) * 4);
            const uint32_t* src = arow + ahalf * 8;
            CPA(dst, src); CPA(dst + 16, src + 4); CPC(); CPW();
        }
        __syncthreads();
        int buf = 0;
        for (int c = 0; c < HM / BK; c++) {
            float4 f0, f1;
            bool pre = (c + 1 < HM / BK);
            if (pre) {
                ldB(W, DM, (c + 1) * BK, nb, tid, f0, f1);
                uint32_t dst = saA + (buf ^ 1) * ABUF_BYTES
                             + (uint32_t)((amf * AST + ahalf * 8) * 4);
                const uint32_t* src = arow + (c + 1) * 16 + ahalf * 8;
                CPA(dst, src); CPA(dst + 16, src + 4); CPC();
            }
            mma_chunk(saA + buf * ABUF_BYTES, saB + buf * BBUF_BYTES,
                      acc, warp_m, warp_n, lane);
            if (pre) stB(Bb + (buf ^ 1) * BBUFW, tid, f0, f1);
            CPW();
            __syncthreads();
            buf ^= 1;
        }
        #pragma unroll
        for (int s = 0; s < 2; s++) {
            int mrow = warp_m * 32 + s * 16 + (lane >> 2);
            #pragma unroll
            for (int nt = 0; nt < 8; nt++) {
                int col = nb + warp_n * 64 + nt * 8 + (lane & 3) * 2;
                float2 bb = *(const float2*)&bv[col];
                if (mrow < rem) {
                    size_t p = (size_t)(start + m0 + mrow);
                    float w = sPw[mrow];
                    *(float2*)&g_po[p * DM + col] =
                        make_float2((acc[s][nt][0] + bb.x) * w,
                                    (acc[s][nt][1] + bb.y) * w);
                }
                if (mrow + 8 < rem) {
                    size_t p = (size_t)(start + m0 + mrow + 8);
                    float w = sPw[mrow + 8];
                    *(float2*)&g_po[p * DM + col] =
                        make_float2((acc[s][nt][2] + bb.x) * w,
                                    (acc[s][nt][3] + bb.y) * w);
                }
            }
        }
    }
}

// ---------------- kernel 9: per-token reduce of 8 pair rows ----------------
__global__ void __launch_bounds__(256) k_reduce(float* __restrict__ out) {
    int t = blockIdx.x, tid = threadIdx.x;
    __shared__ int pos[8];
    if (tid < 8) pos[tid] = g_pos[t * 8 + tid];
    __syncthreads();
    size_t d0 = (size_t)tid * 4;
    float4 s = *(float4*)&out[(size_t)t * DM + d0];
    #pragma unroll
    for (int j = 0; j < 8; j++) {
        float4 v = *(const float4*)&g_po[(size_t)pos[j] * DM + d0];
        s.x += v.x; s.y += v.y; s.z += v.z; s.w += v.w;
    }
    *(float4*)&out[(size_t)t * DM + d0] = s;
}

// ---------------- launcher ----------------
extern "C" void kernel_launch(void* const* d_in, const int* in_sizes, int n_in,
                              void* d_out, int out_size) {
    const float* x      = (const float*)d_in[0];
    const float* norm_w = (const float*)d_in[1];
    const float* Wr     = (const float*)d_in[2];
    const float* sW1    = (const float*)d_in[3];
    const float* sb1    = (const float*)d_in[4];
    const float* sW2    = (const float*)d_in[5];
    const float* sb2    = (const float*)d_in[6];
    const float* sWg    = (const float*)d_in[7];
    const float* rW1    = (const float*)d_in[8];
    const float* rb1    = (const float*)d_in[9];
    const float* rW2    = (const float*)d_in[10];
    const float* rb2    = (const float*)d_in[11];
    const float* rWg    = (const float*)d_in[12];
    const float* bias   = (const float*)d_in[13];
    float* out = (float*)d_out;

    cudaFuncSetAttribute(k_gemm1, cudaFuncAttributeMaxDynamicSharedMemorySize, DSMEM);
    cudaFuncSetAttribute(k_gate,  cudaFuncAttributeMaxDynamicSharedMemorySize, DSMEM);
    cudaFuncSetAttribute(k_gemm2, cudaFuncAttributeMaxDynamicSharedMemorySize, DSMEM);

    k_zero<<<1, 128>>>();
    k_rmsnorm<<<T_TOK, 256>>>(x, norm_w, out);
    k_raw<<<T_TOK / 64, 256>>>(Wr);
    k_topk<<<T_TOK / 8, 256>>>(bias);
    k_scan<<<1, 32>>>();
    k_scatter<<<(NPAIR + 255) / 256, 256>>>();
    k_gemm1<<<dim3(8, HM / BNG, NGRP), 512, DSMEM>>>(rW1, sW1, rb1, sb1);
    k_gate<<<dim3(NPAIR / BMG, HM / BNG), 512, DSMEM>>>(rWg, sWg);
    k_gemm2<<<dim3(8, DM / BNG, NGRP), 512, DSMEM>>>(rW2, sW2, rb2, sb2);
    k_reduce<<<T_TOK, 256>>>(out);
}

// round 6
// speedup vs baseline: 5.1244x; 1.0026x over previous
#include <cuda_runtime.h>
#include <math.h>
#include <stdint.h>

// ---------------- problem constants ----------------
#define T_TOK   2048
#define DM      1024
#define HM      512
#define ER      64
#define TOPK    6
#define ES      2
#define NGRP    (ER + ES)
#define NPAIR_R (T_TOK * TOPK)
#define NPAIR   (NPAIR_R + T_TOK * ES)
#define EPSR    1.1920929e-07f

// ---------------- GEMM tile config ----------------
#define BMG   256                 // block M
#define BNG   128                 // block N
#define BK    64                  // block K
#define AST   36                  // uint32 stride per A row (32 data + 4 pad)
#define BST   68                  // uint32 stride per B k-row (64 data + 4 pad)
#define ABUFW (BMG * AST)
#define BBUFW (BK * BST)
#define ABUF_BYTES (ABUFW * 4)    // 36864
#define BBUF_BYTES (BBUFW * 4)    // 17408
#define BOFF  (2 * ABUF_BYTES)    // 73728
#define XOFF  (BOFF + 2 * BBUF_BYTES) // 108544
#define DSMEM (XOFF + 2048)       // 110592 bytes dynamic smem

// ---------------- device scratch ----------------
__device__ float    g_xn [T_TOK * DM];              // fp32 normed (router only)
__device__ uint32_t g_xnb[T_TOK * DM / 2];          // bf16x2 normed tokens
__device__ int      g_idx[T_TOK * TOPK];
__device__ float    g_wk [T_TOK * TOPK];
__device__ int      g_cnt[NGRP];
__device__ int      g_off[NGRP + 1];
__device__ int      g_fill[ER];
__device__ int      g_ptok[NPAIR];
__device__ float    g_pw  [NPAIR];
__device__ int      g_pos [T_TOK * 8];
__device__ uint32_t g_hb  [(size_t)NPAIR * HM / 2]; // bf16x2 hidden
__device__ uint32_t g_gb  [(size_t)NPAIR * HM / 2]; // bf16x2 gated hidden
__device__ float    g_po  [(size_t)NPAIR * DM];     // fp32 per-pair outputs

// ---------------- PTX helpers ----------------
__device__ __forceinline__ uint32_t pk(float lo, float hi) {
    uint32_t r;
    asm("cvt.rn.bf16x2.f32 %0, %1, %2;" : "=r"(r) : "f"(hi), "f"(lo));
    return r;
}
__device__ __forceinline__ uint32_t cvta(const void* p) {
    return (uint32_t)__cvta_generic_to_shared(p);
}
__device__ __forceinline__ void mma_bf16(float* c, uint32_t a0, uint32_t a1,
                                         uint32_t a2, uint32_t a3,
                                         uint32_t b0, uint32_t b1) {
    asm volatile(
        "mma.sync.aligned.m16n8k16.row.col.f32.bf16.bf16.f32 "
        "{%0,%1,%2,%3}, {%4,%5,%6,%7}, {%8,%9}, {%0,%1,%2,%3};\n"
        : "+f"(c[0]), "+f"(c[1]), "+f"(c[2]), "+f"(c[3])
        : "r"(a0), "r"(a1), "r"(a2), "r"(a3), "r"(b0), "r"(b1));
}
__device__ __forceinline__ void ldsm4(uint32_t& r0, uint32_t& r1, uint32_t& r2,
                                      uint32_t& r3, uint32_t a) {
    asm volatile("ldmatrix.sync.aligned.m8n8.x4.shared.b16 {%0,%1,%2,%3}, [%4];"
                 : "=r"(r0), "=r"(r1), "=r"(r2), "=r"(r3) : "r"(a));
}
__device__ __forceinline__ void ldsm4t(uint32_t& r0, uint32_t& r1, uint32_t& r2,
                                       uint32_t& r3, uint32_t a) {
    asm volatile("ldmatrix.sync.aligned.m8n8.x4.trans.shared.b16 {%0,%1,%2,%3}, [%4];"
                 : "=r"(r0), "=r"(r1), "=r"(r2), "=r"(r3) : "r"(a));
}
#define CPA(dst, src) \
    asm volatile("cp.async.ca.shared.global [%0], [%1], 16;" \
                 :: "r"(dst), "l"(src) : "memory")
#define CPC() asm volatile("cp.async.commit_group;" ::: "memory")
#define CPW() asm volatile("cp.async.wait_group 0;" ::: "memory")

// ---------------- kernel 1: RMSNorm + residual init (+count reset) ----------
__global__ void __launch_bounds__(256) k_rmsnorm(const float* __restrict__ x,
                                                 const float* __restrict__ nw,
                                                 float* __restrict__ out) {
    int t = blockIdx.x, tid = threadIdx.x;
    if (blockIdx.x == 0 && tid < NGRP) g_cnt[tid] = (tid < ER) ? 0 : T_TOK;
    const float4* xr = (const float4*)(x + (size_t)t * DM);
    float4 a = xr[tid];
    float s = a.x * a.x + a.y * a.y + a.z * a.z + a.w * a.w;
    #pragma unroll
    for (int o = 16; o; o >>= 1) s += __shfl_xor_sync(0xffffffffu, s, o);
    __shared__ float ws[8];
    __shared__ float s_scale;
    if ((tid & 31) == 0) ws[tid >> 5] = s;
    __syncthreads();
    if (tid == 0) {
        float tot = 0.f;
        #pragma unroll
        for (int i = 0; i < 8; i++) tot += ws[i];
        s_scale = rsqrtf(tot / (float)DM + EPSR);
    }
    __syncthreads();
    float sc = s_scale;
    float4 w4 = ((const float4*)nw)[tid];
    float4 r;
    r.x = a.x * sc * w4.x; r.y = a.y * sc * w4.y;
    r.z = a.z * sc * w4.z; r.w = a.w * sc * w4.w;
    ((float4*)g_xn)[(size_t)t * 256 + tid] = r;
    ((uint2*)g_xnb)[(size_t)t * 256 + tid] = make_uint2(pk(r.x, r.y), pk(r.z, r.w));
    ((float4*)out)[(size_t)t * 256 + tid]  = a;
}

// ---------------- kernel 2: router (raw affinities fp32 + top-6 fused) ------
#define RPAD 68
__global__ void __launch_bounds__(256) k_route(const float* __restrict__ Wr,
                                               const float* __restrict__ bias) {
    __shared__ float As[16][RPAD];
    __shared__ float Bs[16][RPAD];
    __shared__ float sraw[64][65];
    int t0 = blockIdx.x * 64;
    int tid = threadIdx.x, tx = tid & 15, ty = tid >> 4;
    float acc[4][4];
    #pragma unroll
    for (int i = 0; i < 4; i++)
        #pragma unroll
        for (int j = 0; j < 4; j++) acc[i][j] = 0.f;
    int m = tid >> 2, kv = tid & 3;
    for (int kk = 0; kk < DM; kk += 16) {
        float4 av = *(const float4*)(g_xn + (size_t)(t0 + m) * DM + kk + kv * 4);
        float4 bv = *(const float4*)(Wr + (size_t)m * DM + kk + kv * 4);
        As[kv * 4 + 0][m] = av.x; As[kv * 4 + 1][m] = av.y;
        As[kv * 4 + 2][m] = av.z; As[kv * 4 + 3][m] = av.w;
        Bs[kv * 4 + 0][m] = bv.x; Bs[kv * 4 + 1][m] = bv.y;
        Bs[kv * 4 + 2][m] = bv.z; Bs[kv * 4 + 3][m] = bv.w;
        __syncthreads();
        #pragma unroll
        for (int k = 0; k < 16; k++) {
            float4 a4 = *(float4*)&As[k][ty * 4];
            float4 b4 = *(float4*)&Bs[k][tx * 4];
            float aa[4] = {a4.x, a4.y, a4.z, a4.w};
            float bb[4] = {b4.x, b4.y, b4.z, b4.w};
            #pragma unroll
            for (int i = 0; i < 4; i++)
                #pragma unroll
                for (int j = 0; j < 4; j++) acc[i][j] += aa[i] * bb[j];
        }
        __syncthreads();
    }
    #pragma unroll
    for (int i = 0; i < 4; i++)
        #pragma unroll
        for (int j = 0; j < 4; j++)
            sraw[ty * 4 + i][tx * 4 + j] = acc[i][j];
    __syncthreads();
    // ---- top-6 per token: 8 warps x 8 tokens ----
    int lane = tid & 31, wid = tid >> 5;
    float b0 = bias[lane], b1 = bias[lane + 32];
    #pragma unroll
    for (int q = 0; q < 8; q++) {
        int lt = wid * 8 + q;
        int t = t0 + lt;
        float r0 = sraw[lt][lane];
        float r1 = sraw[lt][lane + 32];
        float a0 = r0 + b0;
        float a1 = r1 + b1;
        float sum = 0.f;
        int   sel_e[TOPK];
        float sel_r[TOPK];
        #pragma unroll
        for (int k = 0; k < TOPK; k++) {
            float v; int e;
            if (a0 >= a1) { v = a0; e = lane; } else { v = a1; e = lane + 32; }
            #pragma unroll
            for (int o = 16; o; o >>= 1) {
                float ov = __shfl_xor_sync(0xffffffffu, v, o);
                int   oe = __shfl_xor_sync(0xffffffffu, e, o);
                if (ov > v || (ov == v && oe < e)) { v = ov; e = oe; }
            }
            if (e == lane)      a0 = -1e30f;
            if (e == lane + 32) a1 = -1e30f;
            float ra = __shfl_sync(0xffffffffu, r0, e & 31);
            float rb = __shfl_sync(0xffffffffu, r1, e & 31);
            float rs = (e < 32) ? ra : rb;
            sel_e[k] = e; sel_r[k] = rs; sum += rs;
        }
        float inv = 1.f / sum;
        if (lane < TOPK) {
            g_idx[t * TOPK + lane] = sel_e[lane];
            g_wk [t * TOPK + lane] = sel_r[lane] * inv;
            atomicAdd(&g_cnt[sel_e[lane]], 1);
        }
    }
}

// ---------------- kernel 3: scan ----------------
__global__ void k_scan() {
    if (threadIdx.x == 0) {
        int acc = 0;
        for (int i = 0; i < NGRP; i++) {
            g_off[i] = acc;
            if (i < ER) g_fill[i] = acc;
            acc += g_cnt[i];
        }
        g_off[NGRP] = acc;
    }
}

// ---------------- kernel 4: scatter ----------------
__global__ void k_scatter() {
    int p = blockIdx.x * 256 + threadIdx.x;
    if (p >= NPAIR) return;
    if (p < NPAIR_R) {
        int t = p / TOPK, k = p % TOPK;
        int e = g_idx[p];
        int pos = atomicAdd(&g_fill[e], 1);
        g_ptok[pos] = t;
        g_pw  [pos] = g_wk[p];
        g_pos[t * 8 + k] = pos;
    } else {
        int q = p - NPAIR_R;
        int j = q / T_TOK, t = q % T_TOK;
        g_ptok[p] = t;
        g_pw  [p] = 1.0f;
        g_pos[t * 8 + TOPK + j] = p;
    }
}

// ================= GEMM core pieces (BK=64) =================
// warp tile 32x64 (2 m16 x 8 n8), 4 ksteps of k16 per chunk
__device__ __forceinline__ void mma_chunk(uint32_t aA, uint32_t aB,
                                          float acc[2][8][4],
                                          int warp_m, int warp_n, int lane) {
    int sel = lane >> 3, li = lane & 7;
    int arow = (sel & 1) * 8 + li;
    int acol = (sel >> 1) * 4;
    int brow = (sel & 1) * 8 + li;
    int bn   = (sel >> 1) * 8;
    #pragma unroll
    for (int ks = 0; ks < 4; ks++) {
        uint32_t a[2][4];
        #pragma unroll
        for (int s = 0; s < 2; s++) {
            uint32_t addr = aA + (uint32_t)(((warp_m * 32 + s * 16 + arow) * AST
                                             + ks * 8 + acol) * 4);
            ldsm4(a[s][0], a[s][1], a[s][2], a[s][3], addr);
        }
        #pragma unroll
        for (int p = 0; p < 4; p++) {
            uint32_t b0, b1, b2, b3;
            uint32_t addr = aB + (uint32_t)((ks * 16 + brow) * (BST * 4)
                                            + (warp_n * 64 + p * 16 + bn) * 2);
            ldsm4t(b0, b1, b2, b3, addr);
            #pragma unroll
            for (int s = 0; s < 2; s++) {
                mma_bf16(acc[s][2 * p],     a[s][0], a[s][1], a[s][2], a[s][3], b0, b1);
                mma_bf16(acc[s][2 * p + 1], a[s][0], a[s][1], a[s][2], a[s][3], b2, b3);
            }
        }
    }
}

// B chunk: 64 k-rows x 128 n fp32 -> 16 regs
__device__ __forceinline__ void ldB(const float* __restrict__ W, int ldb, int kk,
                                    int nb, int tid, float4 f[4]) {
    const float* p = W + (size_t)(kk + (tid >> 3)) * ldb + nb + (tid & 7) * 16;
    f[0] = *(const float4*)p;
    f[1] = *(const float4*)(p + 4);
    f[2] = *(const float4*)(p + 8);
    f[3] = *(const float4*)(p + 12);
}
__device__ __forceinline__ void stB(uint32_t* Bbase, int tid, const float4 f[4]) {
    uint32_t* d = Bbase + (tid >> 3) * BST + (tid & 7) * 8;
    *(uint4*)d = make_uint4(pk(f[0].x, f[0].y), pk(f[0].z, f[0].w),
                            pk(f[1].x, f[1].y), pk(f[1].z, f[1].w));
    *(uint4*)(d + 4) = make_uint4(pk(f[2].x, f[2].y), pk(f[2].z, f[2].w),
                                  pk(f[3].x, f[3].y), pk(f[3].z, f[3].w));
}
// A chunk cp.async: 64B per thread (2 threads per row)
#define CPA4(dstv, srcv) do { \
    uint32_t _d = (dstv); const uint32_t* _s = (srcv); \
    CPA(_d, _s); CPA(_d + 16, _s + 4); CPA(_d + 32, _s + 8); CPA(_d + 48, _s + 12); \
} while (0)

// ---------------- kernel 5: grouped GEMM1 h = gather(xnb) @ W1[e] + b1 ------
__global__ void __launch_bounds__(512, 1)
k_gemm1(const float* __restrict__ rW1, const float* __restrict__ sW1,
        const float* __restrict__ rb1, const float* __restrict__ sb1) {
    extern __shared__ uint8_t dyn[];
    uint32_t* Bb = (uint32_t*)(dyn + BOFF);
    const uint32_t** sArow = (const uint32_t**)(dyn + XOFF);
    uint32_t saA = cvta(dyn), saB = cvta(Bb);
    int grp = blockIdx.z;
    int start = g_off[grp], cnt = g_off[grp + 1] - start;
    const float* W  = (grp < ER) ? rW1 + (size_t)grp * DM * HM
                                 : sW1 + (size_t)(grp - ER) * DM * HM;
    const float* bv = (grp < ER) ? rb1 + (size_t)grp * HM
                                 : sb1 + (size_t)(grp - ER) * HM;
    int nb = blockIdx.y * BNG;
    int tid = threadIdx.x, lane = tid & 31, wid = tid >> 5;
    int warp_m = wid >> 1, warp_n = wid & 1;
    int amf = tid >> 1, ahalf = (tid & 1) * 16;

    for (int mt = blockIdx.x; mt * BMG < cnt; mt += gridDim.x) {
        int m0 = mt * BMG;
        int rem = cnt - m0; if (rem > BMG) rem = BMG;
        __syncthreads();
        if (tid < BMG)
            sArow[tid] = (tid < rem)
                ? g_xnb + (size_t)g_ptok[start + m0 + tid] * (DM / 2) : g_xnb;
        __syncthreads();
        float acc[2][8][4];
        #pragma unroll
        for (int s = 0; s < 2; s++)
            #pragma unroll
            for (int n = 0; n < 8; n++)
                #pragma unroll
                for (int j = 0; j < 4; j++) acc[s][n][j] = 0.f;
        {
            float4 f[4];
            ldB(W, HM, 0, nb, tid, f);
            stB(Bb, tid, f);
            CPA4(saA + (uint32_t)((amf * AST + ahalf) * 4), sArow[amf] + ahalf);
            CPC(); CPW();
        }
        __syncthreads();
        int buf = 0;
        for (int c = 0; c < DM / BK; c++) {
            float4 f[4];
            bool pre = (c + 1 < DM / BK);
            if (pre) {
                ldB(W, HM, (c + 1) * BK, nb, tid, f);
                CPA4(saA + (buf ^ 1) * ABUF_BYTES + (uint32_t)((amf * AST + ahalf) * 4),
                     sArow[amf] + (c + 1) * 32 + ahalf);
                CPC();
            }
            mma_chunk(saA + buf * ABUF_BYTES, saB + buf * BBUF_BYTES,
                      acc, warp_m, warp_n, lane);
            if (pre) stB(Bb + (buf ^ 1) * BBUFW, tid, f);
            CPW();
            __syncthreads();
            buf ^= 1;
        }
        #pragma unroll
        for (int s = 0; s < 2; s++) {
            int mrow = warp_m * 32 + s * 16 + (lane >> 2);
            #pragma unroll
            for (int nt = 0; nt < 8; nt++) {
                int col = nb + warp_n * 64 + nt * 8 + (lane & 3) * 2;
                float2 bb = *(const float2*)&bv[col];
                if (mrow < rem) {
                    size_t p = (size_t)(start + m0 + mrow);
                    g_hb[(p * HM + col) >> 1] =
                        pk(acc[s][nt][0] + bb.x, acc[s][nt][1] + bb.y);
                }
                if (mrow + 8 < rem) {
                    size_t p = (size_t)(start + m0 + mrow + 8);
                    g_hb[(p * HM + col) >> 1] =
                        pk(acc[s][nt][2] + bb.x, acc[s][nt][3] + bb.y);
                }
            }
        }
    }
}

// ---------------- kernel 6: gate  g = silu(h @ Wg) * h ----------------
__global__ void __launch_bounds__(512, 1)
k_gate(const float* __restrict__ rWg, const float* __restrict__ sWg) {
    extern __shared__ uint8_t dyn[];
    uint32_t* Bb = (uint32_t*)(dyn + BOFF);
    uint32_t saA = cvta(dyn), saB = cvta(Bb);
    int p0 = blockIdx.x * BMG;
    const float* W = (p0 < NPAIR_R) ? rWg : sWg;
    int nb = blockIdx.y * BNG;
    int tid = threadIdx.x, lane = tid & 31, wid = tid >> 5;
    int warp_m = wid >> 1, warp_n = wid & 1;
    int amf = tid >> 1, ahalf = (tid & 1) * 16;
    const uint32_t* arow = g_hb + (size_t)(p0 + amf) * (HM / 2);

    float acc[2][8][4];
    #pragma unroll
    for (int s = 0; s < 2; s++)
        #pragma unroll
        for (int n = 0; n < 8; n++)
            #pragma unroll
            for (int j = 0; j < 4; j++) acc[s][n][j] = 0.f;
    {
        float4 f[4];
        ldB(W, HM, 0, nb, tid, f);
        stB(Bb, tid, f);
        CPA4(saA + (uint32_t)((amf * AST + ahalf) * 4), arow + ahalf);
        CPC(); CPW();
    }
    __syncthreads();
    int buf = 0;
    for (int c = 0; c < HM / BK; c++) {
        float4 f[4];
        bool pre = (c + 1 < HM / BK);
        if (pre) {
            ldB(W, HM, (c + 1) * BK, nb, tid, f);
            CPA4(saA + (buf ^ 1) * ABUF_BYTES + (uint32_t)((amf * AST + ahalf) * 4),
                 arow + (c + 1) * 32 + ahalf);
            CPC();
        }
        mma_chunk(saA + buf * ABUF_BYTES, saB + buf * BBUF_BYTES,
                  acc, warp_m, warp_n, lane);
        if (pre) stB(Bb + (buf ^ 1) * BBUFW, tid, f);
        CPW();
        __syncthreads();
        buf ^= 1;
    }
    #pragma unroll
    for (int s = 0; s < 2; s++) {
        int mrow = warp_m * 32 + s * 16 + (lane >> 2);
        #pragma unroll
        for (int nt = 0; nt < 8; nt++) {
            int col = nb + warp_n * 64 + nt * 8 + (lane & 3) * 2;
            #pragma unroll
            for (int hh = 0; hh < 2; hh++) {
                size_t p = (size_t)(p0 + mrow + hh * 8);
                size_t idx = (p * HM + col) >> 1;
                uint32_t hu = g_hb[idx];
                float h0 = __uint_as_float(hu << 16);
                float h1 = __uint_as_float(hu & 0xffff0000u);
                float v0 = acc[s][nt][hh * 2 + 0];
                float v1 = acc[s][nt][hh * 2 + 1];
                float r0 = (v0 / (1.f + __expf(-v0))) * h0;
                float r1 = (v1 / (1.f + __expf(-v1))) * h1;
                g_gb[idx] = pk(r0, r1);
            }
        }
    }
}

// ---------------- kernel 7: grouped GEMM2 po = (g @ W2[e] + b2) * w ----------
__global__ void __launch_bounds__(512, 1)
k_gemm2(const float* __restrict__ rW2, const float* __restrict__ sW2,
        const float* __restrict__ rb2, const float* __restrict__ sb2) {
    extern __shared__ uint8_t dyn[];
    uint32_t* Bb = (uint32_t*)(dyn + BOFF);
    float* sPw = (float*)(dyn + XOFF);
    uint32_t saA = cvta(dyn), saB = cvta(Bb);
    int grp = blockIdx.z;
    int start = g_off[grp], cnt = g_off[grp + 1] - start;
    const float* W  = (grp < ER) ? rW2 + (size_t)grp * HM * DM
                                 : sW2 + (size_t)(grp - ER) * HM * DM;
    const float* bv = (grp < ER) ? rb2 + (size_t)grp * DM
                                 : sb2 + (size_t)(grp - ER) * DM;
    int nb = blockIdx.y * BNG;
    int tid = threadIdx.x, lane = tid & 31, wid = tid >> 5;
    int warp_m = wid >> 1, warp_n = wid & 1;
    int amf = tid >> 1, ahalf = (tid & 1) * 16;

    for (int mt = blockIdx.x; mt * BMG < cnt; mt += gridDim.x) {
        int m0 = mt * BMG;
        int rem = cnt - m0; if (rem > BMG) rem = BMG;
        __syncthreads();
        if (tid < BMG) sPw[tid] = (tid < rem) ? g_pw[start + m0 + tid] : 0.f;
        __syncthreads();
        int ar = amf < rem ? amf : (rem - 1);
        const uint32_t* arow = g_gb + (size_t)(start + m0 + ar) * (HM / 2);
        float acc[2][8][4];
        #pragma unroll
        for (int s = 0; s < 2; s++)
            #pragma unroll
            for (int n = 0; n < 8; n++)
                #pragma unroll
                for (int j = 0; j < 4; j++) acc[s][n][j] = 0.f;
        {
            float4 f[4];
            ldB(W, DM, 0, nb, tid, f);
            stB(Bb, tid, f);
            CPA4(saA + (uint32_t)((amf * AST + ahalf) * 4), arow + ahalf);
            CPC(); CPW();
        }
        __syncthreads();
        int buf = 0;
        for (int c = 0; c < HM / BK; c++) {
            float4 f[4];
            bool pre = (c + 1 < HM / BK);
            if (pre) {
                ldB(W, DM, (c + 1) * BK, nb, tid, f);
                CPA4(saA + (buf ^ 1) * ABUF_BYTES + (uint32_t)((amf * AST + ahalf) * 4),
                     arow + (c + 1) * 32 + ahalf);
                CPC();
            }
            mma_chunk(saA + buf * ABUF_BYTES, saB + buf * BBUF_BYTES,
                      acc, warp_m, warp_n, lane);
            if (pre) stB(Bb + (buf ^ 1) * BBUFW, tid, f);
            CPW();
            __syncthreads();
            buf ^= 1;
        }
        #pragma unroll
        for (int s = 0; s < 2; s++) {
            int mrow = warp_m * 32 + s * 16 + (lane >> 2);
            #pragma unroll
            for (int nt = 0; nt < 8; nt++) {
                int col = nb + warp_n * 64 + nt * 8 + (lane & 3) * 2;
                float2 bb = *(const float2*)&bv[col];
                if (mrow < rem) {
                    size_t p = (size_t)(start + m0 + mrow);
                    float w = sPw[mrow];
                    *(float2*)&g_po[p * DM + col] =
                        make_float2((acc[s][nt][0] + bb.x) * w,
                                    (acc[s][nt][1] + bb.y) * w);
                }
                if (mrow + 8 < rem) {
                    size_t p = (size_t)(start + m0 + mrow + 8);
                    float w = sPw[mrow + 8];
                    *(float2*)&g_po[p * DM + col] =
                        make_float2((acc[s][nt][2] + bb.x) * w,
                                    (acc[s][nt][3] + bb.y) * w);
                }
            }
        }
    }
}

// ---------------- kernel 8: per-token reduce of 8 pair rows ----------------
__global__ void __launch_bounds__(256) k_reduce(float* __restrict__ out) {
    int t = blockIdx.x, tid = threadIdx.x;
    __shared__ int pos[8];
    if (tid < 8) pos[tid] = g_pos[t * 8 + tid];
    __syncthreads();
    size_t d0 = (size_t)tid * 4;
    float4 s = *(float4*)&out[(size_t)t * DM + d0];
    #pragma unroll
    for (int j = 0; j < 8; j++) {
        float4 v = *(const float4*)&g_po[(size_t)pos[j] * DM + d0];
        s.x += v.x; s.y += v.y; s.z += v.z; s.w += v.w;
    }
    *(float4*)&out[(size_t)t * DM + d0] = s;
}

// ---------------- launcher ----------------
extern "C" void kernel_launch(void* const* d_in, const int* in_sizes, int n_in,
                              void* d_out, int out_size) {
    const float* x      = (const float*)d_in[0];
    const float* norm_w = (const float*)d_in[1];
    const float* Wr     = (const float*)d_in[2];
    const float* sW1    = (const float*)d_in[3];
    const float* sb1    = (const float*)d_in[4];
    const float* sW2    = (const float*)d_in[5];
    const float* sb2    = (const float*)d_in[6];
    const float* sWg    = (const float*)d_in[7];
    const float* rW1    = (const float*)d_in[8];
    const float* rb1    = (const float*)d_in[9];
    const float* rW2    = (const float*)d_in[10];
    const float* rb2    = (const float*)d_in[11];
    const float* rWg    = (const float*)d_in[12];
    const float* bias   = (const float*)d_in[13];
    float* out = (float*)d_out;

    cudaFuncSetAttribute(k_gemm1, cudaFuncAttributeMaxDynamicSharedMemorySize, DSMEM);
    cudaFuncSetAttribute(k_gate,  cudaFuncAttributeMaxDynamicSharedMemorySize, DSMEM);
    cudaFuncSetAttribute(k_gemm2, cudaFuncAttributeMaxDynamicSharedMemorySize, DSMEM);

    k_rmsnorm<<<T_TOK, 256>>>(x, norm_w, out);
    k_route<<<T_TOK / 64, 256>>>(Wr, bias);
    k_scan<<<1, 32>>>();
    k_scatter<<<(NPAIR + 255) / 256, 256>>>();
    k_gemm1<<<dim3(8, HM / BNG, NGRP), 512, DSMEM>>>(rW1, sW1, rb1, sb1);
    k_gate<<<dim3(NPAIR / BMG, HM / BNG), 512, DSMEM>>>(rWg, sWg);
    k_gemm2<<<dim3(8, DM / BNG, NGRP), 512, DSMEM>>>(rW2, sW2, rb2, sb2);
    k_reduce<<<T_TOK, 256>>>(out);
}

// round 7
// speedup vs baseline: 5.2963x; 1.0335x over previous
#include <cuda_runtime.h>
#include <math.h>
#include <stdint.h>

// ---------------- problem constants ----------------
#define T_TOK   2048
#define DM      1024
#define HM      512
#define ER      64
#define TOPK    6
#define ES      2
#define NGRP    (ER + ES)
#define NPAIR_R (T_TOK * TOPK)
#define NPAIR   (NPAIR_R + T_TOK * ES)
#define EPSR    1.1920929e-07f

// ---------------- GEMM tile config ----------------
#define BMG   256                 // block M
#define BNG   128                 // block N
#define BK    64                  // block K
#define AST   36                  // uint32 stride per A row (32 data + 4 pad)
#define BST   68                  // uint32 stride per B k-row (64 data + 4 pad)
#define ABUFW (BMG * AST)
#define BBUFW (BK * BST)
#define ABUF_BYTES (ABUFW * 4)    // 36864
#define BBUF_BYTES (BBUFW * 4)    // 17408
#define BOFF  (2 * ABUF_BYTES)    // 73728
#define XOFF  (BOFF + 2 * BBUF_BYTES) // 108544
#define DSMEM (XOFF + 2048)       // 110592 bytes dynamic smem

// ---------------- device scratch ----------------
__device__ float    g_xn [T_TOK * DM];              // fp32 normed (router only)
__device__ uint32_t g_xnb[T_TOK * DM / 2];          // bf16x2 normed tokens
__device__ int      g_idx[T_TOK * TOPK];
__device__ float    g_wk [T_TOK * TOPK];
__device__ int      g_cnt[NGRP];
__device__ int      g_off[NGRP + 1];
__device__ int      g_fill[ER];
__device__ int      g_ptok[NPAIR];
__device__ float    g_pw  [NPAIR];
__device__ int      g_pos [T_TOK * 8];
__device__ uint32_t g_hb  [(size_t)NPAIR * HM / 2]; // bf16x2 hidden
__device__ uint32_t g_gb  [(size_t)NPAIR * HM / 2]; // bf16x2 gated hidden
__device__ float    g_po  [(size_t)NPAIR * DM];     // fp32 per-pair outputs

// ---------------- PTX helpers ----------------
__device__ __forceinline__ uint32_t pk(float lo, float hi) {
    uint32_t r;
    asm("cvt.rn.bf16x2.f32 %0, %1, %2;" : "=r"(r) : "f"(hi), "f"(lo));
    return r;
}
__device__ __forceinline__ uint32_t cvta(const void* p) {
    return (uint32_t)__cvta_generic_to_shared(p);
}
__device__ __forceinline__ void mma_bf16(float* c, uint32_t a0, uint32_t a1,
                                         uint32_t a2, uint32_t a3,
                                         uint32_t b0, uint32_t b1) {
    asm volatile(
        "mma.sync.aligned.m16n8k16.row.col.f32.bf16.bf16.f32 "
        "{%0,%1,%2,%3}, {%4,%5,%6,%7}, {%8,%9}, {%0,%1,%2,%3};\n"
        : "+f"(c[0]), "+f"(c[1]), "+f"(c[2]), "+f"(c[3])
        : "r"(a0), "r"(a1), "r"(a2), "r"(a3), "r"(b0), "r"(b1));
}
__device__ __forceinline__ void ldsm4(uint32_t& r0, uint32_t& r1, uint32_t& r2,
                                      uint32_t& r3, uint32_t a) {
    asm volatile("ldmatrix.sync.aligned.m8n8.x4.shared.b16 {%0,%1,%2,%3}, [%4];"
                 : "=r"(r0), "=r"(r1), "=r"(r2), "=r"(r3) : "r"(a));
}
__device__ __forceinline__ void ldsm4t(uint32_t& r0, uint32_t& r1, uint32_t& r2,
                                       uint32_t& r3, uint32_t a) {
    asm volatile("ldmatrix.sync.aligned.m8n8.x4.trans.shared.b16 {%0,%1,%2,%3}, [%4];"
                 : "=r"(r0), "=r"(r1), "=r"(r2), "=r"(r3) : "r"(a));
}
#define CPA(dst, src) \
    asm volatile("cp.async.ca.shared.global [%0], [%1], 16;" \
                 :: "r"(dst), "l"(src) : "memory")
#define CPC() asm volatile("cp.async.commit_group;" ::: "memory")
#define CPW() asm volatile("cp.async.wait_group 0;" ::: "memory")

// ---------------- kernel 1: RMSNorm + residual init (+counter reset) --------
__global__ void __launch_bounds__(256) k_rmsnorm(const float* __restrict__ x,
                                                 const float* __restrict__ nw,
                                                 float* __restrict__ out) {
    int t = blockIdx.x, tid = threadIdx.x;
    if (blockIdx.x == 0) {
        if (tid < NGRP) g_cnt[tid] = (tid < ER) ? 0 : T_TOK;
        if (tid >= 128 && tid < 128 + ER) g_fill[tid - 128] = 0;
    }
    const float4* xr = (const float4*)(x + (size_t)t * DM);
    float4 a = xr[tid];
    float s = a.x * a.x + a.y * a.y + a.z * a.z + a.w * a.w;
    #pragma unroll
    for (int o = 16; o; o >>= 1) s += __shfl_xor_sync(0xffffffffu, s, o);
    __shared__ float ws[8];
    __shared__ float s_scale;
    if ((tid & 31) == 0) ws[tid >> 5] = s;
    __syncthreads();
    if (tid == 0) {
        float tot = 0.f;
        #pragma unroll
        for (int i = 0; i < 8; i++) tot += ws[i];
        s_scale = rsqrtf(tot / (float)DM + EPSR);
    }
    __syncthreads();
    float sc = s_scale;
    float4 w4 = ((const float4*)nw)[tid];
    float4 r;
    r.x = a.x * sc * w4.x; r.y = a.y * sc * w4.y;
    r.z = a.z * sc * w4.z; r.w = a.w * sc * w4.w;
    ((float4*)g_xn)[(size_t)t * 256 + tid] = r;
    ((uint2*)g_xnb)[(size_t)t * 256 + tid] = make_uint2(pk(r.x, r.y), pk(r.z, r.w));
    ((float4*)out)[(size_t)t * 256 + tid]  = a;
}

// ---------------- kernel 2: router (raw affinities fp32 + top-6 fused) ------
#define RPAD 68
__global__ void __launch_bounds__(256) k_route(const float* __restrict__ Wr,
                                               const float* __restrict__ bias) {
    __shared__ float As[16][RPAD];
    __shared__ float Bs[16][RPAD];
    __shared__ float sraw[64][65];
    int t0 = blockIdx.x * 64;
    int tid = threadIdx.x, tx = tid & 15, ty = tid >> 4;
    float acc[4][4];
    #pragma unroll
    for (int i = 0; i < 4; i++)
        #pragma unroll
        for (int j = 0; j < 4; j++) acc[i][j] = 0.f;
    int m = tid >> 2, kv = tid & 3;
    for (int kk = 0; kk < DM; kk += 16) {
        float4 av = *(const float4*)(g_xn + (size_t)(t0 + m) * DM + kk + kv * 4);
        float4 bv = *(const float4*)(Wr + (size_t)m * DM + kk + kv * 4);
        As[kv * 4 + 0][m] = av.x; As[kv * 4 + 1][m] = av.y;
        As[kv * 4 + 2][m] = av.z; As[kv * 4 + 3][m] = av.w;
        Bs[kv * 4 + 0][m] = bv.x; Bs[kv * 4 + 1][m] = bv.y;
        Bs[kv * 4 + 2][m] = bv.z; Bs[kv * 4 + 3][m] = bv.w;
        __syncthreads();
        #pragma unroll
        for (int k = 0; k < 16; k++) {
            float4 a4 = *(float4*)&As[k][ty * 4];
            float4 b4 = *(float4*)&Bs[k][tx * 4];
            float aa[4] = {a4.x, a4.y, a4.z, a4.w};
            float bb[4] = {b4.x, b4.y, b4.z, b4.w};
            #pragma unroll
            for (int i = 0; i < 4; i++)
                #pragma unroll
                for (int j = 0; j < 4; j++) acc[i][j] += aa[i] * bb[j];
        }
        __syncthreads();
    }
    #pragma unroll
    for (int i = 0; i < 4; i++)
        #pragma unroll
        for (int j = 0; j < 4; j++)
            sraw[ty * 4 + i][tx * 4 + j] = acc[i][j];
    __syncthreads();
    int lane = tid & 31, wid = tid >> 5;
    float b0 = bias[lane], b1 = bias[lane + 32];
    #pragma unroll
    for (int q = 0; q < 8; q++) {
        int lt = wid * 8 + q;
        int t = t0 + lt;
        float r0 = sraw[lt][lane];
        float r1 = sraw[lt][lane + 32];
        float a0 = r0 + b0;
        float a1 = r1 + b1;
        float sum = 0.f;
        int   sel_e[TOPK];
        float sel_r[TOPK];
        #pragma unroll
        for (int k = 0; k < TOPK; k++) {
            float v; int e;
            if (a0 >= a1) { v = a0; e = lane; } else { v = a1; e = lane + 32; }
            #pragma unroll
            for (int o = 16; o; o >>= 1) {
                float ov = __shfl_xor_sync(0xffffffffu, v, o);
                int   oe = __shfl_xor_sync(0xffffffffu, e, o);
                if (ov > v || (ov == v && oe < e)) { v = ov; e = oe; }
            }
            if (e == lane)      a0 = -1e30f;
            if (e == lane + 32) a1 = -1e30f;
            float ra = __shfl_sync(0xffffffffu, r0, e & 31);
            float rb = __shfl_sync(0xffffffffu, r1, e & 31);
            float rs = (e < 32) ? ra : rb;
            sel_e[k] = e; sel_r[k] = rs; sum += rs;
        }
        float inv = 1.f / sum;
        if (lane < TOPK) {
            g_idx[t * TOPK + lane] = sel_e[lane];
            g_wk [t * TOPK + lane] = sel_r[lane] * inv;
            atomicAdd(&g_cnt[sel_e[lane]], 1);
        }
    }
}

// ---------------- kernel 3: scatter (with fused per-block scan) ------------
__global__ void __launch_bounds__(256) k_scatter() {
    __shared__ int s_off[NGRP + 1];
    int tid = threadIdx.x;
    if (tid == 0) {
        int acc = 0;
        #pragma unroll
        for (int i = 0; i < NGRP; i++) { s_off[i] = acc; acc += g_cnt[i]; }
        s_off[NGRP] = acc;
    }
    __syncthreads();
    if (blockIdx.x == 0 && tid <= NGRP) g_off[tid] = s_off[tid];
    int p = blockIdx.x * 256 + tid;
    if (p >= NPAIR) return;
    if (p < NPAIR_R) {
        int t = p / TOPK, k = p % TOPK;
        int e = g_idx[p];
        int pos = s_off[e] + atomicAdd(&g_fill[e], 1);
        g_ptok[pos] = t;
        g_pw  [pos] = g_wk[p];
        g_pos[t * 8 + k] = pos;
    } else {
        int q = p - NPAIR_R;
        int j = q / T_TOK, t = q % T_TOK;
        int pos = s_off[ER + j] + t;
        g_ptok[pos] = t;
        g_pw  [pos] = 1.0f;
        g_pos[t * 8 + TOPK + j] = pos;
    }
}

// ================= GEMM core pieces (BK=64) =================
__device__ __forceinline__ void mma_chunk(uint32_t aA, uint32_t aB,
                                          float acc[2][8][4],
                                          int warp_m, int warp_n, int lane) {
    int sel = lane >> 3, li = lane & 7;
    int arow = (sel & 1) * 8 + li;
    int acol = (sel >> 1) * 4;
    int brow = (sel & 1) * 8 + li;
    int bn   = (sel >> 1) * 8;
    #pragma unroll
    for (int ks = 0; ks < 4; ks++) {
        uint32_t a[2][4];
        #pragma unroll
        for (int s = 0; s < 2; s++) {
            uint32_t addr = aA + (uint32_t)(((warp_m * 32 + s * 16 + arow) * AST
                                             + ks * 8 + acol) * 4);
            ldsm4(a[s][0], a[s][1], a[s][2], a[s][3], addr);
        }
        #pragma unroll
        for (int p = 0; p < 4; p++) {
            uint32_t b0, b1, b2, b3;
            uint32_t addr = aB + (uint32_t)((ks * 16 + brow) * (BST * 4)
                                            + (warp_n * 64 + p * 16 + bn) * 2);
            ldsm4t(b0, b1, b2, b3, addr);
            #pragma unroll
            for (int s = 0; s < 2; s++) {
                mma_bf16(acc[s][2 * p],     a[s][0], a[s][1], a[s][2], a[s][3], b0, b1);
                mma_bf16(acc[s][2 * p + 1], a[s][0], a[s][1], a[s][2], a[s][3], b2, b3);
            }
        }
    }
}

__device__ __forceinline__ void ldB(const float* __restrict__ W, int ldb, int kk,
                                    int nb, int tid, float4 f[4]) {
    const float* p = W + (size_t)(kk + (tid >> 3)) * ldb + nb + (tid & 7) * 16;
    f[0] = *(const float4*)p;
    f[1] = *(const float4*)(p + 4);
    f[2] = *(const float4*)(p + 8);
    f[3] = *(const float4*)(p + 12);
}
__device__ __forceinline__ void stB(uint32_t* Bbase, int tid, const float4 f[4]) {
    uint32_t* d = Bbase + (tid >> 3) * BST + (tid & 7) * 8;
    *(uint4*)d = make_uint4(pk(f[0].x, f[0].y), pk(f[0].z, f[0].w),
                            pk(f[1].x, f[1].y), pk(f[1].z, f[1].w));
    *(uint4*)(d + 4) = make_uint4(pk(f[2].x, f[2].y), pk(f[2].z, f[2].w),
                                  pk(f[3].x, f[3].y), pk(f[3].z, f[3].w));
}
#define CPA4(dstv, srcv) do { \
    uint32_t _d = (dstv); const uint32_t* _s = (srcv); \
    CPA(_d, _s); CPA(_d + 16, _s + 4); CPA(_d + 32, _s + 8); CPA(_d + 48, _s + 12); \
} while (0)

// ---------------- kernel 4: grouped GEMM1 h = gather(xnb) @ W1[e] + b1 ------
__global__ void __launch_bounds__(512, 1)
k_gemm1(const float* __restrict__ rW1, const float* __restrict__ sW1,
        const float* __restrict__ rb1, const float* __restrict__ sb1) {
    extern __shared__ uint8_t dyn[];
    uint32_t* Bb = (uint32_t*)(dyn + BOFF);
    const uint32_t** sArow = (const uint32_t**)(dyn + XOFF);
    uint32_t saA = cvta(dyn), saB = cvta(Bb);
    int grp = blockIdx.z;
    int start = g_off[grp], cnt = g_off[grp + 1] - start;
    const float* W  = (grp < ER) ? rW1 + (size_t)grp * DM * HM
                                 : sW1 + (size_t)(grp - ER) * DM * HM;
    const float* bv = (grp < ER) ? rb1 + (size_t)grp * HM
                                 : sb1 + (size_t)(grp - ER) * HM;
    int nb = blockIdx.y * BNG;
    int tid = threadIdx.x, lane = tid & 31, wid = tid >> 5;
    int warp_m = wid >> 1, warp_n = wid & 1;
    int amf = tid >> 1, ahalf = (tid & 1) * 16;

    for (int mt = blockIdx.x; mt * BMG < cnt; mt += gridDim.x) {
        int m0 = mt * BMG;
        int rem = cnt - m0; if (rem > BMG) rem = BMG;
        bool active = (warp_m * 32 < rem);   // skip mma for fully-padded warps
        __syncthreads();
        if (tid < BMG)
            sArow[tid] = (tid < rem)
                ? g_xnb + (size_t)g_ptok[start + m0 + tid] * (DM / 2) : g_xnb;
        __syncthreads();
        float acc[2][8][4];
        #pragma unroll
        for (int s = 0; s < 2; s++)
            #pragma unroll
            for (int n = 0; n < 8; n++)
                #pragma unroll
                for (int j = 0; j < 4; j++) acc[s][n][j] = 0.f;
        {
            float4 f[4];
            ldB(W, HM, 0, nb, tid, f);
            stB(Bb, tid, f);
            CPA4(saA + (uint32_t)((amf * AST + ahalf) * 4), sArow[amf] + ahalf);
            CPC(); CPW();
        }
        __syncthreads();
        int buf = 0;
        for (int c = 0; c < DM / BK; c++) {
            float4 f[4];
            bool pre = (c + 1 < DM / BK);
            if (pre) {
                ldB(W, HM, (c + 1) * BK, nb, tid, f);
                CPA4(saA + (buf ^ 1) * ABUF_BYTES + (uint32_t)((amf * AST + ahalf) * 4),
                     sArow[amf] + (c + 1) * 32 + ahalf);
                CPC();
            }
            if (active)
                mma_chunk(saA + buf * ABUF_BYTES, saB + buf * BBUF_BYTES,
                          acc, warp_m, warp_n, lane);
            if (pre) stB(Bb + (buf ^ 1) * BBUFW, tid, f);
            CPW();
            __syncthreads();
            buf ^= 1;
        }
        if (active) {
            #pragma unroll
            for (int s = 0; s < 2; s++) {
                int mrow = warp_m * 32 + s * 16 + (lane >> 2);
                #pragma unroll
                for (int nt = 0; nt < 8; nt++) {
                    int col = nb + warp_n * 64 + nt * 8 + (lane & 3) * 2;
                    float2 bb = *(const float2*)&bv[col];
                    if (mrow < rem) {
                        size_t p = (size_t)(start + m0 + mrow);
                        g_hb[(p * HM + col) >> 1] =
                            pk(acc[s][nt][0] + bb.x, acc[s][nt][1] + bb.y);
                    }
                    if (mrow + 8 < rem) {
                        size_t p = (size_t)(start + m0 + mrow + 8);
                        g_hb[(p * HM + col) >> 1] =
                            pk(acc[s][nt][2] + bb.x, acc[s][nt][3] + bb.y);
                    }
                }
            }
        }
    }
}

// ---------------- kernel 5: gate  g = silu(h @ Wg) * h ----------------
__global__ void __launch_bounds__(512, 1)
k_gate(const float* __restrict__ rWg, const float* __restrict__ sWg) {
    extern __shared__ uint8_t dyn[];
    uint32_t* Bb = (uint32_t*)(dyn + BOFF);
    uint32_t saA = cvta(dyn), saB = cvta(Bb);
    int p0 = blockIdx.x * BMG;
    const float* W = (p0 < NPAIR_R) ? rWg : sWg;
    int nb = blockIdx.y * BNG;
    int tid = threadIdx.x, lane = tid & 31, wid = tid >> 5;
    int warp_m = wid >> 1, warp_n = wid & 1;
    int amf = tid >> 1, ahalf = (tid & 1) * 16;
    const uint32_t* arow = g_hb + (size_t)(p0 + amf) * (HM / 2);

    float acc[2][8][4];
    #pragma unroll
    for (int s = 0; s < 2; s++)
        #pragma unroll
        for (int n = 0; n < 8; n++)
            #pragma unroll
            for (int j = 0; j < 4; j++) acc[s][n][j] = 0.f;
    {
        float4 f[4];
        ldB(W, HM, 0, nb, tid, f);
        stB(Bb, tid, f);
        CPA4(saA + (uint32_t)((amf * AST + ahalf) * 4), arow + ahalf);
        CPC(); CPW();
    }
    __syncthreads();
    int buf = 0;
    for (int c = 0; c < HM / BK; c++) {
        float4 f[4];
        bool pre = (c + 1 < HM / BK);
        if (pre) {
            ldB(W, HM, (c + 1) * BK, nb, tid, f);
            CPA4(saA + (buf ^ 1) * ABUF_BYTES + (uint32_t)((amf * AST + ahalf) * 4),
                 arow + (c + 1) * 32 + ahalf);
            CPC();
        }
        mma_chunk(saA + buf * ABUF_BYTES, saB + buf * BBUF_BYTES,
                  acc, warp_m, warp_n, lane);
        if (pre) stB(Bb + (buf ^ 1) * BBUFW, tid, f);
        CPW();
        __syncthreads();
        buf ^= 1;
    }
    #pragma unroll
    for (int s = 0; s < 2; s++) {
        int mrow = warp_m * 32 + s * 16 + (lane >> 2);
        #pragma unroll
        for (int nt = 0; nt < 8; nt++) {
            int col = nb + warp_n * 64 + nt * 8 + (lane & 3) * 2;
            #pragma unroll
            for (int hh = 0; hh < 2; hh++) {
                size_t p = (size_t)(p0 + mrow + hh * 8);
                size_t idx = (p * HM + col) >> 1;
                uint32_t hu = g_hb[idx];
                float h0 = __uint_as_float(hu << 16);
                float h1 = __uint_as_float(hu & 0xffff0000u);
                float v0 = acc[s][nt][hh * 2 + 0];
                float v1 = acc[s][nt][hh * 2 + 1];
                float r0 = (v0 / (1.f + __expf(-v0))) * h0;
                float r1 = (v1 / (1.f + __expf(-v1))) * h1;
                g_gb[idx] = pk(r0, r1);
            }
        }
    }
}

// ---------------- kernel 6: grouped GEMM2 po = (g @ W2[e] + b2) * w ----------
__global__ void __launch_bounds__(512, 1)
k_gemm2(const float* __restrict__ rW2, const float* __restrict__ sW2,
        const float* __restrict__ rb2, const float* __restrict__ sb2) {
    extern __shared__ uint8_t dyn[];
    uint32_t* Bb = (uint32_t*)(dyn + BOFF);
    float* sPw = (float*)(dyn + XOFF);
    uint32_t saA = cvta(dyn), saB = cvta(Bb);
    int grp = blockIdx.z;
    int start = g_off[grp], cnt = g_off[grp + 1] - start;
    const float* W  = (grp < ER) ? rW2 + (size_t)grp * HM * DM
                                 : sW2 + (size_t)(grp - ER) * HM * DM;
    const float* bv = (grp < ER) ? rb2 + (size_t)grp * DM
                                 : sb2 + (size_t)(grp - ER) * DM;
    int nb = blockIdx.y * BNG;
    int tid = threadIdx.x, lane = tid & 31, wid = tid >> 5;
    int warp_m = wid >> 1, warp_n = wid & 1;
    int amf = tid >> 1, ahalf = (tid & 1) * 16;

    for (int mt = blockIdx.x; mt * BMG < cnt; mt += gridDim.x) {
        int m0 = mt * BMG;
        int rem = cnt - m0; if (rem > BMG) rem = BMG;
        bool active = (warp_m * 32 < rem);
        __syncthreads();
        if (tid < BMG) sPw[tid] = (tid < rem) ? g_pw[start + m0 + tid] : 0.f;
        __syncthreads();
        int ar = amf < rem ? amf : (rem - 1);
        const uint32_t* arow = g_gb + (size_t)(start + m0 + ar) * (HM / 2);
        float acc[2][8][4];
        #pragma unroll
        for (int s = 0; s < 2; s++)
            #pragma unroll
            for (int n = 0; n < 8; n++)
                #pragma unroll
                for (int j = 0; j < 4; j++) acc[s][n][j] = 0.f;
        {
            float4 f[4];
            ldB(W, DM, 0, nb, tid, f);
            stB(Bb, tid, f);
            CPA4(saA + (uint32_t)((amf * AST + ahalf) * 4), arow + ahalf);
            CPC(); CPW();
        }
        __syncthreads();
        int buf = 0;
        for (int c = 0; c < HM / BK; c++) {
            float4 f[4];
            bool pre = (c + 1 < HM / BK);
            if (pre) {
                ldB(W, DM, (c + 1) * BK, nb, tid, f);
                CPA4(saA + (buf ^ 1) * ABUF_BYTES + (uint32_t)((amf * AST + ahalf) * 4),
                     arow + (c + 1) * 32 + ahalf);
                CPC();
            }
            if (active)
                mma_chunk(saA + buf * ABUF_BYTES, saB + buf * BBUF_BYTES,
                          acc, warp_m, warp_n, lane);
            if (pre) stB(Bb + (buf ^ 1) * BBUFW, tid, f);
            CPW();
            __syncthreads();
            buf ^= 1;
        }
        if (active) {
            #pragma unroll
            for (int s = 0; s < 2; s++) {
                int mrow = warp_m * 32 + s * 16 + (lane >> 2);
                #pragma unroll
                for (int nt = 0; nt < 8; nt++) {
                    int col = nb + warp_n * 64 + nt * 8 + (lane & 3) * 2;
                    float2 bb = *(const float2*)&bv[col];
                    if (mrow < rem) {
                        size_t p = (size_t)(start + m0 + mrow);
                        float w = sPw[mrow];
                        *(float2*)&g_po[p * DM + col] =
                            make_float2((acc[s][nt][0] + bb.x) * w,
                                        (acc[s][nt][1] + bb.y) * w);
                    }
                    if (mrow + 8 < rem) {
                        size_t p = (size_t)(start + m0 + mrow + 8);
                        float w = sPw[mrow + 8];
                        *(float2*)&g_po[p * DM + col] =
                            make_float2((acc[s][nt][2] + bb.x) * w,
                                        (acc[s][nt][3] + bb.y) * w);
                    }
                }
            }
        }
    }
}

// ---------------- kernel 7: per-token reduce of 8 pair rows ----------------
__global__ void __launch_bounds__(256) k_reduce(float* __restrict__ out) {
    int t = blockIdx.x, tid = threadIdx.x;
    __shared__ int pos[8];
    if (tid < 8) pos[tid] = g_pos[t * 8 + tid];
    __syncthreads();
    size_t d0 = (size_t)tid * 4;
    float4 s = *(float4*)&out[(size_t)t * DM + d0];
    #pragma unroll
    for (int j = 0; j < 8; j++) {
        float4 v = *(const float4*)&g_po[(size_t)pos[j] * DM + d0];
        s.x += v.x; s.y += v.y; s.z += v.z; s.w += v.w;
    }
    *(float4*)&out[(size_t)t * DM + d0] = s;
}

// ---------------- launcher ----------------
extern "C" void kernel_launch(void* const* d_in, const int* in_sizes, int n_in,
                              void* d_out, int out_size) {
    const float* x      = (const float*)d_in[0];
    const float* norm_w = (const float*)d_in[1];
    const float* Wr     = (const float*)d_in[2];
    const float* sW1    = (const float*)d_in[3];
    const float* sb1    = (const float*)d_in[4];
    const float* sW2    = (const float*)d_in[5];
    const float* sb2    = (const float*)d_in[6];
    const float* sWg    = (const float*)d_in[7];
    const float* rW1    = (const float*)d_in[8];
    const float* rb1    = (const float*)d_in[9];
    const float* rW2    = (const float*)d_in[10];
    const float* rb2    = (const float*)d_in[11];
    const float* rWg    = (const float*)d_in[12];
    const float* bias   = (const float*)d_in[13];
    float* out = (float*)d_out;

    cudaFuncSetAttribute(k_gemm1, cudaFuncAttributeMaxDynamicSharedMemorySize, DSMEM);
    cudaFuncSetAttribute(k_gate,  cudaFuncAttributeMaxDynamicSharedMemorySize, DSMEM);
    cudaFuncSetAttribute(k_gemm2, cudaFuncAttributeMaxDynamicSharedMemorySize, DSMEM);

    k_rmsnorm<<<T_TOK, 256>>>(x, norm_w, out);
    k_route<<<T_TOK / 64, 256>>>(Wr, bias);
    k_scatter<<<(NPAIR + 255) / 256, 256>>>();
    k_gemm1<<<dim3(8, HM / BNG, NGRP), 512, DSMEM>>>(rW1, sW1, rb1, sb1);
    k_gate<<<dim3(NPAIR / BMG, HM / BNG), 512, DSMEM>>>(rWg, sWg);
    k_gemm2<<<dim3(8, DM / BNG, NGRP), 512, DSMEM>>>(rW2, sW2, rb2, sb2);
    k_reduce<<<T_TOK, 256>>>(out);
}